// round 1
// baseline (speedup 1.0000x reference)
#include <cuda_runtime.h>
#include <cstdint>

// ---------------------------------------------------------------------------
// ProductionFastMQA: x[B,S,2048] -> Q/K/V proj -> MQA attention -> O proj
// B=2, S=2048, HIDDEN=2048, HEADS=16, HEAD_DIM=128 (single shared KV head)
//
// Strategy (round 1): one generic batched/strided TF32 mma.sync GEMM with
// 3xTF32 (hi/lo split) for ~fp32 precision, scores materialized + standalone
// softmax kernel. All scratch in __device__ globals (no allocation).
// ---------------------------------------------------------------------------

#define HIDDEN   2048
#define HEADS    16
#define HEAD_DIM 128
#define BB       2
#define SS       2048
#define SCALE    0.08838834764831845f   // 1/sqrt(128)

#define BM 128
#define BN 128
#define BK 16

// Scratch (device globals — allocation-free per harness rules)
__device__ float g_q[BB * SS * HIDDEN];            // 33.5 MB  [B,S,2048]
__device__ float g_k[BB * SS * HEAD_DIM];          // 2 MB     [B,S,128]
__device__ float g_v[BB * SS * HEAD_DIM];          // 2 MB
__device__ float g_scores[(long long)BB * HEADS * SS * SS]; // 536 MB [B,H,S,S]
__device__ float g_attn[BB * SS * HIDDEN];         // 33.5 MB  [B,S,H*D]

// ---------------------------------------------------------------------------

__device__ __forceinline__ uint32_t tf32_rna(float x) {
    uint32_t r;
    asm("cvt.rna.tf32.f32 %0, %1;" : "=r"(r) : "f"(x));
    return r;
}

__device__ __forceinline__ void tf32_split(float x, uint32_t& hi, uint32_t& lo) {
    hi = tf32_rna(x);
    lo = tf32_rna(x - __uint_as_float(hi));
}

__device__ __forceinline__ void mma8(float* c, const uint32_t* a, const uint32_t* b) {
    asm volatile(
        "mma.sync.aligned.m16n8k8.row.col.f32.tf32.tf32.f32 "
        "{%0,%1,%2,%3},{%4,%5,%6,%7},{%8,%9},{%0,%1,%2,%3};"
        : "+f"(c[0]), "+f"(c[1]), "+f"(c[2]), "+f"(c[3])
        : "r"(a[0]), "r"(a[1]), "r"(a[2]), "r"(a[3]),
          "r"(b[0]), "r"(b[1]));
}

// C[M,N] = alpha * A[M,K] * op(B).   A row-major (lda).
// B_NK=true : B stored [N,K] row-major (ldb = row stride) -> C = A * B^T
// B_NK=false: B stored [K,N] row-major (ldb)              -> C = A * B
// Batch: z = blockIdx.z; zb = z/hdiv, zh = z%hdiv; each operand offset by
// zb*XB + zh*XH. All dims must be multiples of the tile sizes (they are here).
template <bool B_NK>
__global__ __launch_bounds__(256) void gemm3t(
    const float* __restrict__ A, const float* __restrict__ B, float* __restrict__ C,
    int M, int N, int K, int lda, int ldb, int ldc,
    long long aB, long long aH, long long bB, long long bH,
    long long cB, long long cH, int hdiv, float alpha)
{
    __shared__ uint32_t AsH[BM][BK + 4], AsL[BM][BK + 4];
    __shared__ uint32_t BsH[BK][BN + 8], BsL[BK][BN + 8];

    const int z  = blockIdx.z;
    const int zb = z / hdiv, zh = z % hdiv;
    A += zb * aB + zh * aH;
    B += zb * bB + zh * bH;
    C += zb * cB + zh * cH;

    const int tid  = threadIdx.x;
    const int lane = tid & 31;
    const int warp = tid >> 5;
    const int lr   = lane >> 2;   // 0..7
    const int lc   = lane & 3;    // 0..3
    const int wm0  = (warp >> 2) * 64;  // warp rows: 2
    const int wn0  = (warp & 3) * 32;   // warp cols: 4

    const int m0 = blockIdx.y * BM;
    const int n0 = blockIdx.x * BN;

    float acc[4][4][4];
#pragma unroll
    for (int mi = 0; mi < 4; mi++)
#pragma unroll
        for (int ni = 0; ni < 4; ni++)
#pragma unroll
            for (int q = 0; q < 4; q++) acc[mi][ni][q] = 0.f;

    for (int kt = 0; kt < K; kt += BK) {
        // ---- load A tile: 128 x 16 floats (512 float4, 2 per thread) ----
#pragma unroll
        for (int i = 0; i < 2; i++) {
            int idx = tid + i * 256;          // 0..511
            int r   = idx >> 2;               // 4 float4 per row
            int c4  = (idx & 3) * 4;
            float4 v = *(const float4*)(A + (long long)(m0 + r) * lda + kt + c4);
            uint32_t h, l;
            tf32_split(v.x, h, l); AsH[r][c4 + 0] = h; AsL[r][c4 + 0] = l;
            tf32_split(v.y, h, l); AsH[r][c4 + 1] = h; AsL[r][c4 + 1] = l;
            tf32_split(v.z, h, l); AsH[r][c4 + 2] = h; AsL[r][c4 + 2] = l;
            tf32_split(v.w, h, l); AsH[r][c4 + 3] = h; AsL[r][c4 + 3] = l;
        }
        // ---- load B tile ----
        if (B_NK) {
            // B stored [N,K]: tile = 128 n-rows x 16 k (512 float4), transpose into Bs[k][n]
#pragma unroll
            for (int i = 0; i < 2; i++) {
                int idx = tid + i * 256;
                int r   = idx >> 2;           // n within tile
                int c4  = (idx & 3) * 4;      // k within tile
                float4 v = *(const float4*)(B + (long long)(n0 + r) * ldb + kt + c4);
                uint32_t h, l;
                tf32_split(v.x, h, l); BsH[c4 + 0][r] = h; BsL[c4 + 0][r] = l;
                tf32_split(v.y, h, l); BsH[c4 + 1][r] = h; BsL[c4 + 1][r] = l;
                tf32_split(v.z, h, l); BsH[c4 + 2][r] = h; BsL[c4 + 2][r] = l;
                tf32_split(v.w, h, l); BsH[c4 + 3][r] = h; BsL[c4 + 3][r] = l;
            }
        } else {
            // B stored [K,N]: tile = 16 k-rows x 128 n (512 float4), direct
#pragma unroll
            for (int i = 0; i < 2; i++) {
                int idx = tid + i * 256;
                int r   = idx >> 5;           // k within tile (32 float4 per row)
                int c4  = (idx & 31) * 4;     // n within tile
                float4 v = *(const float4*)(B + (long long)(kt + r) * ldb + n0 + c4);
                uint32_t h, l;
                tf32_split(v.x, h, l); BsH[r][c4 + 0] = h; BsL[r][c4 + 0] = l;
                tf32_split(v.y, h, l); BsH[r][c4 + 1] = h; BsL[r][c4 + 1] = l;
                tf32_split(v.z, h, l); BsH[r][c4 + 2] = h; BsL[r][c4 + 2] = l;
                tf32_split(v.w, h, l); BsH[r][c4 + 3] = h; BsL[r][c4 + 3] = l;
            }
        }
        __syncthreads();

#pragma unroll
        for (int kk = 0; kk < BK; kk += 8) {
            uint32_t ah[4][4], al[4][4], bh[4][2], bl[4][2];
#pragma unroll
            for (int mi = 0; mi < 4; mi++) {
                int m = wm0 + mi * 16;
                ah[mi][0] = AsH[m + lr][kk + lc];
                ah[mi][1] = AsH[m + lr + 8][kk + lc];
                ah[mi][2] = AsH[m + lr][kk + lc + 4];
                ah[mi][3] = AsH[m + lr + 8][kk + lc + 4];
                al[mi][0] = AsL[m + lr][kk + lc];
                al[mi][1] = AsL[m + lr + 8][kk + lc];
                al[mi][2] = AsL[m + lr][kk + lc + 4];
                al[mi][3] = AsL[m + lr + 8][kk + lc + 4];
            }
#pragma unroll
            for (int ni = 0; ni < 4; ni++) {
                int n = wn0 + ni * 8 + lr;
                bh[ni][0] = BsH[kk + lc][n];
                bh[ni][1] = BsH[kk + lc + 4][n];
                bl[ni][0] = BsL[kk + lc][n];
                bl[ni][1] = BsL[kk + lc + 4][n];
            }
#pragma unroll
            for (int mi = 0; mi < 4; mi++)
#pragma unroll
                for (int ni = 0; ni < 4; ni++) {
                    mma8(acc[mi][ni], ah[mi], bh[ni]);   // hi*hi
                    mma8(acc[mi][ni], ah[mi], bl[ni]);   // hi*lo
                    mma8(acc[mi][ni], al[mi], bh[ni]);   // lo*hi
                }
        }
        __syncthreads();
    }

    // ---- epilogue ----
#pragma unroll
    for (int mi = 0; mi < 4; mi++) {
#pragma unroll
        for (int ni = 0; ni < 4; ni++) {
            int row = m0 + wm0 + mi * 16 + lr;
            int col = n0 + wn0 + ni * 8 + 2 * lc;
            float2 v0 = make_float2(alpha * acc[mi][ni][0], alpha * acc[mi][ni][1]);
            float2 v1 = make_float2(alpha * acc[mi][ni][2], alpha * acc[mi][ni][3]);
            *(float2*)(C + (long long)row * ldc + col)       = v0;
            *(float2*)(C + (long long)(row + 8) * ldc + col) = v1;
        }
    }
}

// ---------------------------------------------------------------------------
// Row softmax, row length exactly 2048, one 256-thread CTA per row.
// ---------------------------------------------------------------------------
__global__ __launch_bounds__(256) void softmax2048(float* __restrict__ S) {
    float* row = S + (long long)blockIdx.x * 2048;
    const int tid  = threadIdx.x;
    const int lane = tid & 31;
    const int warp = tid >> 5;
    __shared__ float red[8];

    float4 v0 = ((const float4*)row)[tid];
    float4 v1 = ((const float4*)row)[tid + 256];

    float m = fmaxf(fmaxf(fmaxf(v0.x, v0.y), fmaxf(v0.z, v0.w)),
                    fmaxf(fmaxf(v1.x, v1.y), fmaxf(v1.z, v1.w)));
#pragma unroll
    for (int o = 16; o; o >>= 1) m = fmaxf(m, __shfl_xor_sync(0xffffffffu, m, o));
    if (lane == 0) red[warp] = m;
    __syncthreads();
    float mx = red[0];
#pragma unroll
    for (int i = 1; i < 8; i++) mx = fmaxf(mx, red[i]);
    __syncthreads();

    v0.x = __expf(v0.x - mx); v0.y = __expf(v0.y - mx);
    v0.z = __expf(v0.z - mx); v0.w = __expf(v0.w - mx);
    v1.x = __expf(v1.x - mx); v1.y = __expf(v1.y - mx);
    v1.z = __expf(v1.z - mx); v1.w = __expf(v1.w - mx);

    float s = v0.x + v0.y + v0.z + v0.w + v1.x + v1.y + v1.z + v1.w;
#pragma unroll
    for (int o = 16; o; o >>= 1) s += __shfl_xor_sync(0xffffffffu, s, o);
    if (lane == 0) red[warp] = s;
    __syncthreads();
    float tot = red[0] + red[1] + red[2] + red[3] + red[4] + red[5] + red[6] + red[7];
    float inv = 1.0f / tot;

    v0.x *= inv; v0.y *= inv; v0.z *= inv; v0.w *= inv;
    v1.x *= inv; v1.y *= inv; v1.z *= inv; v1.w *= inv;
    ((float4*)row)[tid]       = v0;
    ((float4*)row)[tid + 256] = v1;
}

// ---------------------------------------------------------------------------

extern "C" void kernel_launch(void* const* d_in, const int* in_sizes, int n_in,
                              void* d_out, int out_size) {
    const float* x  = (const float*)d_in[0];   // [B,S,2048]
    const float* qw = (const float*)d_in[1];   // [2048,2048]
    const float* kw = (const float*)d_in[2];   // [128,2048]
    const float* vw = (const float*)d_in[3];   // [128,2048]
    const float* ow = (const float*)d_in[4];   // [2048,2048]
    float* out = (float*)d_out;                // [B,S,2048]

    float *q, *k, *v, *sc, *at;
    cudaGetSymbolAddress((void**)&q,  g_q);
    cudaGetSymbolAddress((void**)&k,  g_k);
    cudaGetSymbolAddress((void**)&v,  g_v);
    cudaGetSymbolAddress((void**)&sc, g_scores);
    cudaGetSymbolAddress((void**)&at, g_attn);

    const long long SH  = (long long)SS * HIDDEN;     // 4194304  (per-batch x/q/attn stride)
    const long long SD  = (long long)SS * HEAD_DIM;   // 262144   (per-batch k/v stride)
    const long long SSq = (long long)SS * SS;         // 4194304  (per-head scores stride)

    // 1) Q = X @ Qw^T   [4096,2048]
    gemm3t<true><<<dim3(HIDDEN / BN, (BB * SS) / BM, 1), 256>>>(
        x, qw, q, BB * SS, HIDDEN, HIDDEN, HIDDEN, HIDDEN, HIDDEN,
        0, 0, 0, 0, 0, 0, 1, 1.0f);
    // 2) K = X @ Kw^T   [4096,128]
    gemm3t<true><<<dim3(HEAD_DIM / BN, (BB * SS) / BM, 1), 256>>>(
        x, kw, k, BB * SS, HEAD_DIM, HIDDEN, HIDDEN, HIDDEN, HEAD_DIM,
        0, 0, 0, 0, 0, 0, 1, 1.0f);
    // 3) V = X @ Vw^T   [4096,128]
    gemm3t<true><<<dim3(HEAD_DIM / BN, (BB * SS) / BM, 1), 256>>>(
        x, vw, v, BB * SS, HEAD_DIM, HIDDEN, HIDDEN, HIDDEN, HEAD_DIM,
        0, 0, 0, 0, 0, 0, 1, 1.0f);
    // 4) scores[b,h] = SCALE * Q[b,:,h*128:(h+1)*128] @ K[b]^T   [2048,2048] x32
    gemm3t<true><<<dim3(SS / BN, SS / BM, BB * HEADS), 256>>>(
        q, k, sc, SS, SS, HEAD_DIM, HIDDEN, HEAD_DIM, SS,
        SH, HEAD_DIM, SD, 0, (long long)HEADS * SSq, SSq, HEADS, SCALE);
    // 5) softmax rows
    softmax2048<<<BB * HEADS * SS, 256>>>(sc);
    // 6) attn[b,:,h*128:(h+1)*128] = P[b,h] @ V[b]   [2048,128] x32
    gemm3t<false><<<dim3(HEAD_DIM / BN, SS / BM, BB * HEADS), 256>>>(
        sc, v, at, SS, HEAD_DIM, SS, SS, HEAD_DIM, HIDDEN,
        (long long)HEADS * SSq, SSq, SD, 0, SH, HEAD_DIM, HEADS, 1.0f);
    // 7) out = attn @ Ow^T   [4096,2048]
    gemm3t<true><<<dim3(HIDDEN / BN, (BB * SS) / BM, 1), 256>>>(
        at, ow, out, BB * SS, HIDDEN, HIDDEN, HIDDEN, HIDDEN, HIDDEN,
        0, 0, 0, 0, 0, 0, 1, 1.0f);
}

// round 2
// speedup vs baseline: 2.7904x; 2.7904x over previous
#include <cuda_runtime.h>
#include <cuda_bf16.h>
#include <cstdint>

// ---------------------------------------------------------------------------
// ProductionFastMQA round 2: bf16x3 (hi/lo split) mma.m16n8k16 GEMMs with
// cp.async double buffering + ldmatrix. Same 7-launch structure as round 1.
// ---------------------------------------------------------------------------

#define HIDDEN   2048
#define HEADS    16
#define HEAD_DIM 128
#define BB       2
#define SS       2048
#define SCALE    0.08838834764831845f   // 1/sqrt(128)

#define BM   128
#define BN   128
#define BKb  32                 // bf16 K per tile
#define ASTR (BKb + 8)          // 40 bf16 row stride (80B: conflict-free ldmatrix)
#define BSTR_KN (BN + 8)        // 136 bf16 (272B)
#define ASZ  (BM * ASTR)        // 5120 elems per (stage,h) A tile
#define BSZ_NK (BN * ASTR)      // 5120
#define BSZ_KN (BKb * BSTR_KN)  // 4352

#define SMEM_NK ((4*ASZ + 4*BSZ_NK) * 2)   // 81920 B
#define SMEM_KN ((4*ASZ + 4*BSZ_KN) * 2)   // 75776 B

// ----------------------------- scratch (device globals) --------------------
__device__ __nv_bfloat16 g_xh[BB*SS*HIDDEN],  g_xl[BB*SS*HIDDEN];
__device__ __nv_bfloat16 g_qwh[HIDDEN*HIDDEN], g_qwl[HIDDEN*HIDDEN];
__device__ __nv_bfloat16 g_kwh[HEAD_DIM*HIDDEN], g_kwl[HEAD_DIM*HIDDEN];
__device__ __nv_bfloat16 g_vwh[HEAD_DIM*HIDDEN], g_vwl[HEAD_DIM*HIDDEN];
__device__ __nv_bfloat16 g_owh[HIDDEN*HIDDEN], g_owl[HIDDEN*HIDDEN];
__device__ __nv_bfloat16 g_qh[BB*SS*HIDDEN],  g_ql[BB*SS*HIDDEN];
__device__ __nv_bfloat16 g_kh[BB*SS*HEAD_DIM], g_kl[BB*SS*HEAD_DIM];
__device__ __nv_bfloat16 g_vh[BB*SS*HEAD_DIM], g_vl[BB*SS*HEAD_DIM];
__device__ float         g_scores[(long long)BB*HEADS*SS*SS];       // 536 MB
__device__ __nv_bfloat16 g_ph[(long long)BB*HEADS*SS*SS];           // 268 MB
__device__ __nv_bfloat16 g_pl[(long long)BB*HEADS*SS*SS];           // 268 MB
__device__ __nv_bfloat16 g_ath[BB*SS*HIDDEN], g_atl[BB*SS*HIDDEN];

// ----------------------------- PTX helpers ---------------------------------
__device__ __forceinline__ void ldm4(uint32_t* r, uint32_t a) {
    asm volatile("ldmatrix.sync.aligned.m8n8.x4.shared.b16 {%0,%1,%2,%3},[%4];"
                 : "=r"(r[0]), "=r"(r[1]), "=r"(r[2]), "=r"(r[3]) : "r"(a));
}
__device__ __forceinline__ void ldm4t(uint32_t* r, uint32_t a) {
    asm volatile("ldmatrix.sync.aligned.m8n8.x4.trans.shared.b16 {%0,%1,%2,%3},[%4];"
                 : "=r"(r[0]), "=r"(r[1]), "=r"(r[2]), "=r"(r[3]) : "r"(a));
}
__device__ __forceinline__ void cpa16(uint32_t d, const void* s) {
    asm volatile("cp.async.cg.shared.global [%0],[%1],16;" :: "r"(d), "l"(s));
}
__device__ __forceinline__ void mma16(float* c, const uint32_t* a, const uint32_t* b) {
    asm volatile(
        "mma.sync.aligned.m16n8k16.row.col.f32.bf16.bf16.f32 "
        "{%0,%1,%2,%3},{%4,%5,%6,%7},{%8,%9},{%0,%1,%2,%3};"
        : "+f"(c[0]), "+f"(c[1]), "+f"(c[2]), "+f"(c[3])
        : "r"(a[0]), "r"(a[1]), "r"(a[2]), "r"(a[3]), "r"(b[0]), "r"(b[1]));
}

// ---------------------------------------------------------------------------
// Generic batched/strided bf16x3 GEMM.
//  C = alpha * A * op(B), A = Ah+Al [M,K] row-major.
//  B_NK=true : B [N,K] row-major -> C = A*B^T ; false: B [K,N] -> C = A*B
//  OUT_PAIR  : write Chi/Clo bf16 split instead of fp32 C.
// ---------------------------------------------------------------------------
template <bool B_NK, bool OUT_PAIR>
__global__ __launch_bounds__(256) void gemm_bf3(
    const __nv_bfloat16* __restrict__ Ah, const __nv_bfloat16* __restrict__ Al,
    const __nv_bfloat16* __restrict__ Bh, const __nv_bfloat16* __restrict__ Bl,
    float* __restrict__ C, __nv_bfloat16* __restrict__ Chi, __nv_bfloat16* __restrict__ Clo,
    int K, int lda, int ldb, int ldc,
    long long aB, long long aH, long long bB, long long bH,
    long long cB, long long cH, int hdiv, float alpha)
{
    extern __shared__ __nv_bfloat16 sm[];
    const int BSZ = B_NK ? BSZ_NK : BSZ_KN;
    __nv_bfloat16* Asm = sm;
    __nv_bfloat16* Bsm = sm + 4 * ASZ;
    const uint32_t as_base = (uint32_t)__cvta_generic_to_shared(Asm);
    const uint32_t bs_base = (uint32_t)__cvta_generic_to_shared(Bsm);

    const int z = blockIdx.z;
    const int zb = z / hdiv, zh = z - zb * hdiv;
    Ah += zb * aB + zh * aH;  Al += zb * aB + zh * aH;
    Bh += zb * bB + zh * bH;  Bl += zb * bB + zh * bH;
    const long long coff = zb * cB + zh * cH;

    const int tid = threadIdx.x, lane = tid & 31, warp = tid >> 5;
    const int wm0 = (warp >> 2) * 64;
    const int wn0 = (warp & 3) * 32;
    const int m0 = blockIdx.y * BM, n0 = blockIdx.x * BN;

    float acc[4][4][4] = {};

    const int ar = tid >> 2;           // A/B-NK load row (per 256-chunk)
    const int ac = (tid & 3) * 8;      // col (bf16)

    auto ld_stage = [&](int kt, int st) {
#pragma unroll
        for (int i = 0; i < 2; i++) {
            int r = ar + i * 64;
            long long go = (long long)(m0 + r) * lda + kt + ac;
            uint32_t so = (uint32_t)(r * ASTR + ac) * 2;
            cpa16(as_base + (st*2+0)*ASZ*2 + so, Ah + go);
            cpa16(as_base + (st*2+1)*ASZ*2 + so, Al + go);
        }
        if (B_NK) {
#pragma unroll
            for (int i = 0; i < 2; i++) {
                int r = ar + i * 64;
                long long go = (long long)(n0 + r) * ldb + kt + ac;
                uint32_t so = (uint32_t)(r * ASTR + ac) * 2;
                cpa16(bs_base + (st*2+0)*BSZ_NK*2 + so, Bh + go);
                cpa16(bs_base + (st*2+1)*BSZ_NK*2 + so, Bl + go);
            }
        } else {
#pragma unroll
            for (int i = 0; i < 2; i++) {
                int idx = tid + i * 256;
                int r = idx >> 4, c = (idx & 15) * 8;
                long long go = (long long)(kt + r) * ldb + n0 + c;
                uint32_t so = (uint32_t)(r * BSTR_KN + c) * 2;
                cpa16(bs_base + (st*2+0)*BSZ_KN*2 + so, Bh + go);
                cpa16(bs_base + (st*2+1)*BSZ_KN*2 + so, Bl + go);
            }
        }
    };

    ld_stage(0, 0);
    asm volatile("cp.async.commit_group;");

    const int T = K / BKb;
    for (int t = 0; t < T; t++) {
        if (t + 1 < T) {
            ld_stage((t + 1) * BKb, (t + 1) & 1);
            asm volatile("cp.async.commit_group;");
            asm volatile("cp.async.wait_group 1;");
        } else {
            asm volatile("cp.async.wait_group 0;");
        }
        __syncthreads();
        const int st = t & 1;
        const uint32_t aH0 = as_base + (st*2+0)*ASZ*2;
        const uint32_t aL0 = as_base + (st*2+1)*ASZ*2;
        const uint32_t bH0 = bs_base + (st*2+0)*BSZ*2;
        const uint32_t bL0 = bs_base + (st*2+1)*BSZ*2;

#pragma unroll
        for (int kk = 0; kk < BKb; kk += 16) {
            uint32_t ah[4][4], al[4][4];
            const int arow = wm0 + (lane & 15);
            const int acol = kk + ((lane >> 4) << 3);
#pragma unroll
            for (int mi = 0; mi < 4; mi++) {
                uint32_t off = (uint32_t)((arow + mi*16) * ASTR + acol) * 2;
                ldm4(ah[mi], aH0 + off);
                ldm4(al[mi], aL0 + off);
            }
            uint32_t bh[4][2], bl[4][2];
            if (B_NK) {
                const int br = wn0 + ((lane >> 4) << 3) + (lane & 7);
                const int bc = kk + (((lane >> 3) & 1) << 3);
#pragma unroll
                for (int j = 0; j < 2; j++) {
                    uint32_t off = (uint32_t)((br + j*16) * ASTR + bc) * 2;
                    uint32_t r4[4];
                    ldm4(r4, bH0 + off);
                    bh[2*j][0]=r4[0]; bh[2*j][1]=r4[1]; bh[2*j+1][0]=r4[2]; bh[2*j+1][1]=r4[3];
                    ldm4(r4, bL0 + off);
                    bl[2*j][0]=r4[0]; bl[2*j][1]=r4[1]; bl[2*j+1][0]=r4[2]; bl[2*j+1][1]=r4[3];
                }
            } else {
                const int bk = kk + (((lane >> 3) & 1) << 3) + (lane & 7);
                const int bn = wn0 + ((lane >> 4) << 3);
#pragma unroll
                for (int j = 0; j < 2; j++) {
                    uint32_t off = (uint32_t)(bk * BSTR_KN + bn + j*16) * 2;
                    uint32_t r4[4];
                    ldm4t(r4, bH0 + off);
                    bh[2*j][0]=r4[0]; bh[2*j][1]=r4[1]; bh[2*j+1][0]=r4[2]; bh[2*j+1][1]=r4[3];
                    ldm4t(r4, bL0 + off);
                    bl[2*j][0]=r4[0]; bl[2*j][1]=r4[1]; bl[2*j+1][0]=r4[2]; bl[2*j+1][1]=r4[3];
                }
            }
#pragma unroll
            for (int mi = 0; mi < 4; mi++)
#pragma unroll
                for (int ni = 0; ni < 4; ni++) {
                    mma16(acc[mi][ni], ah[mi], bh[ni]);
                    mma16(acc[mi][ni], ah[mi], bl[ni]);
                    mma16(acc[mi][ni], al[mi], bh[ni]);
                }
        }
        __syncthreads();
    }

    // epilogue
    const int lr = lane >> 2, lc = lane & 3;
#pragma unroll
    for (int mi = 0; mi < 4; mi++) {
#pragma unroll
        for (int ni = 0; ni < 4; ni++) {
            const int row = m0 + wm0 + mi*16 + lr;
            const int col = n0 + wn0 + ni*8 + 2*lc;
            if (OUT_PAIR) {
#pragma unroll
                for (int hf = 0; hf < 2; hf++) {
                    float c0 = alpha * acc[mi][ni][2*hf];
                    float c1 = alpha * acc[mi][ni][2*hf + 1];
                    __nv_bfloat16 h0 = __float2bfloat16(c0);
                    __nv_bfloat16 l0 = __float2bfloat16(c0 - __bfloat162float(h0));
                    __nv_bfloat16 h1 = __float2bfloat16(c1);
                    __nv_bfloat16 l1 = __float2bfloat16(c1 - __bfloat162float(h1));
                    long long o = coff + (long long)(row + 8*hf) * ldc + col;
                    __nv_bfloat162 hh; hh.x = h0; hh.y = h1;
                    __nv_bfloat162 ll; ll.x = l0; ll.y = l1;
                    *(__nv_bfloat162*)(Chi + o) = hh;
                    *(__nv_bfloat162*)(Clo + o) = ll;
                }
            } else {
                long long o = coff + (long long)row * ldc + col;
                *(float2*)(C + o) =
                    make_float2(alpha * acc[mi][ni][0], alpha * acc[mi][ni][1]);
                *(float2*)(C + o + 8LL * ldc) =
                    make_float2(alpha * acc[mi][ni][2], alpha * acc[mi][ni][3]);
            }
        }
    }
}

// ------------------------- fp32 -> bf16 hi/lo split -------------------------
__global__ __launch_bounds__(256) void splitk(
    const float* __restrict__ in, __nv_bfloat16* __restrict__ hi,
    __nv_bfloat16* __restrict__ lo, int n4)
{
    int i = blockIdx.x * 256 + threadIdx.x;
    if (i >= n4) return;
    float4 v = ((const float4*)in)[i];
    __nv_bfloat16 h0 = __float2bfloat16(v.x), h1 = __float2bfloat16(v.y);
    __nv_bfloat16 h2 = __float2bfloat16(v.z), h3 = __float2bfloat16(v.w);
    __nv_bfloat162 a, b, c, d;
    a.x = h0; a.y = h1; b.x = h2; b.y = h3;
    c.x = __float2bfloat16(v.x - __bfloat162float(h0));
    c.y = __float2bfloat16(v.y - __bfloat162float(h1));
    d.x = __float2bfloat16(v.z - __bfloat162float(h2));
    d.y = __float2bfloat16(v.w - __bfloat162float(h3));
    ((__nv_bfloat162*)hi)[2*i]     = a;
    ((__nv_bfloat162*)hi)[2*i + 1] = b;
    ((__nv_bfloat162*)lo)[2*i]     = c;
    ((__nv_bfloat162*)lo)[2*i + 1] = d;
}

// -------- row softmax (len 2048), writes P as bf16 hi/lo pair ---------------
__global__ __launch_bounds__(256) void softmax_pair(
    const float* __restrict__ S, __nv_bfloat16* __restrict__ Ph,
    __nv_bfloat16* __restrict__ Pl)
{
    const float* row = S + (long long)blockIdx.x * 2048;
    const int tid = threadIdx.x, lane = tid & 31, warp = tid >> 5;
    __shared__ float red[8];

    float4 v0 = ((const float4*)row)[tid];
    float4 v1 = ((const float4*)row)[tid + 256];

    float m = fmaxf(fmaxf(fmaxf(v0.x, v0.y), fmaxf(v0.z, v0.w)),
                    fmaxf(fmaxf(v1.x, v1.y), fmaxf(v1.z, v1.w)));
#pragma unroll
    for (int o = 16; o; o >>= 1) m = fmaxf(m, __shfl_xor_sync(0xffffffffu, m, o));
    if (lane == 0) red[warp] = m;
    __syncthreads();
    float mx = red[0];
#pragma unroll
    for (int i = 1; i < 8; i++) mx = fmaxf(mx, red[i]);
    __syncthreads();

    v0.x = __expf(v0.x - mx); v0.y = __expf(v0.y - mx);
    v0.z = __expf(v0.z - mx); v0.w = __expf(v0.w - mx);
    v1.x = __expf(v1.x - mx); v1.y = __expf(v1.y - mx);
    v1.z = __expf(v1.z - mx); v1.w = __expf(v1.w - mx);

    float s = v0.x + v0.y + v0.z + v0.w + v1.x + v1.y + v1.z + v1.w;
#pragma unroll
    for (int o = 16; o; o >>= 1) s += __shfl_xor_sync(0xffffffffu, s, o);
    if (lane == 0) red[warp] = s;
    __syncthreads();
    float inv = 1.0f / (red[0]+red[1]+red[2]+red[3]+red[4]+red[5]+red[6]+red[7]);

    __nv_bfloat16* ph = Ph + (long long)blockIdx.x * 2048;
    __nv_bfloat16* pl = Pl + (long long)blockIdx.x * 2048;
    float e[8] = {v0.x*inv, v0.y*inv, v0.z*inv, v0.w*inv,
                  v1.x*inv, v1.y*inv, v1.z*inv, v1.w*inv};
#pragma unroll
    for (int g = 0; g < 2; g++) {
        __nv_bfloat162 hh0, hh1, ll0, ll1;
        float a0 = e[4*g+0], a1 = e[4*g+1], a2 = e[4*g+2], a3 = e[4*g+3];
        hh0.x = __float2bfloat16(a0); hh0.y = __float2bfloat16(a1);
        hh1.x = __float2bfloat16(a2); hh1.y = __float2bfloat16(a3);
        ll0.x = __float2bfloat16(a0 - __bfloat162float(hh0.x));
        ll0.y = __float2bfloat16(a1 - __bfloat162float(hh0.y));
        ll1.x = __float2bfloat16(a2 - __bfloat162float(hh1.x));
        ll1.y = __float2bfloat16(a3 - __bfloat162float(hh1.y));
        int base = g ? (512 + 2*tid) : (2*tid);
        ((__nv_bfloat162*)ph)[base]     = hh0;
        ((__nv_bfloat162*)ph)[base + 1] = hh1;
        ((__nv_bfloat162*)pl)[base]     = ll0;
        ((__nv_bfloat162*)pl)[base + 1] = ll1;
    }
}

// ---------------------------------------------------------------------------

extern "C" void kernel_launch(void* const* d_in, const int* in_sizes, int n_in,
                              void* d_out, int out_size) {
    const float* x  = (const float*)d_in[0];
    const float* qw = (const float*)d_in[1];
    const float* kw = (const float*)d_in[2];
    const float* vw = (const float*)d_in[3];
    const float* ow = (const float*)d_in[4];
    float* out = (float*)d_out;

    __nv_bfloat16 *xh,*xl,*qwh,*qwl,*kwh,*kwl,*vwh,*vwl,*owh,*owl;
    __nv_bfloat16 *qh,*ql,*kh,*kl,*vh,*vl,*ph,*pl,*ath,*atl;
    float *sc;
    cudaGetSymbolAddress((void**)&xh,  g_xh);  cudaGetSymbolAddress((void**)&xl,  g_xl);
    cudaGetSymbolAddress((void**)&qwh, g_qwh); cudaGetSymbolAddress((void**)&qwl, g_qwl);
    cudaGetSymbolAddress((void**)&kwh, g_kwh); cudaGetSymbolAddress((void**)&kwl, g_kwl);
    cudaGetSymbolAddress((void**)&vwh, g_vwh); cudaGetSymbolAddress((void**)&vwl, g_vwl);
    cudaGetSymbolAddress((void**)&owh, g_owh); cudaGetSymbolAddress((void**)&owl, g_owl);
    cudaGetSymbolAddress((void**)&qh,  g_qh);  cudaGetSymbolAddress((void**)&ql,  g_ql);
    cudaGetSymbolAddress((void**)&kh,  g_kh);  cudaGetSymbolAddress((void**)&kl,  g_kl);
    cudaGetSymbolAddress((void**)&vh,  g_vh);  cudaGetSymbolAddress((void**)&vl,  g_vl);
    cudaGetSymbolAddress((void**)&ph,  g_ph);  cudaGetSymbolAddress((void**)&pl,  g_pl);
    cudaGetSymbolAddress((void**)&ath, g_ath); cudaGetSymbolAddress((void**)&atl, g_atl);
    cudaGetSymbolAddress((void**)&sc,  g_scores);

    cudaFuncSetAttribute((const void*)gemm_bf3<true,  true >,
                         cudaFuncAttributeMaxDynamicSharedMemorySize, SMEM_NK);
    cudaFuncSetAttribute((const void*)gemm_bf3<true,  false>,
                         cudaFuncAttributeMaxDynamicSharedMemorySize, SMEM_NK);
    cudaFuncSetAttribute((const void*)gemm_bf3<false, true >,
                         cudaFuncAttributeMaxDynamicSharedMemorySize, SMEM_KN);

    const long long SH  = (long long)SS * HIDDEN;
    const long long SD  = (long long)SS * HEAD_DIM;
    const long long SSq = (long long)SS * SS;

    // 0) splits of inputs/weights
    splitk<<<(BB*SS*HIDDEN/4 + 255)/256, 256>>>(x,  xh,  xl,  BB*SS*HIDDEN/4);
    splitk<<<(HIDDEN*HIDDEN/4 + 255)/256, 256>>>(qw, qwh, qwl, HIDDEN*HIDDEN/4);
    splitk<<<(HEAD_DIM*HIDDEN/4 + 255)/256, 256>>>(kw, kwh, kwl, HEAD_DIM*HIDDEN/4);
    splitk<<<(HEAD_DIM*HIDDEN/4 + 255)/256, 256>>>(vw, vwh, vwl, HEAD_DIM*HIDDEN/4);
    splitk<<<(HIDDEN*HIDDEN/4 + 255)/256, 256>>>(ow, owh, owl, HIDDEN*HIDDEN/4);

    // 1) Q = X @ Qw^T  -> pair
    gemm_bf3<true, true><<<dim3(HIDDEN/BN, (BB*SS)/BM, 1), 256, SMEM_NK>>>(
        xh, xl, qwh, qwl, nullptr, qh, ql,
        HIDDEN, HIDDEN, HIDDEN, HIDDEN, 0,0,0,0,0,0, 1, 1.0f);
    // 2) K = X @ Kw^T  -> pair
    gemm_bf3<true, true><<<dim3(HEAD_DIM/BN, (BB*SS)/BM, 1), 256, SMEM_NK>>>(
        xh, xl, kwh, kwl, nullptr, kh, kl,
        HIDDEN, HIDDEN, HIDDEN, HEAD_DIM, 0,0,0,0,0,0, 1, 1.0f);
    // 3) V = X @ Vw^T  -> pair
    gemm_bf3<true, true><<<dim3(HEAD_DIM/BN, (BB*SS)/BM, 1), 256, SMEM_NK>>>(
        xh, xl, vwh, vwl, nullptr, vh, vl,
        HIDDEN, HIDDEN, HIDDEN, HEAD_DIM, 0,0,0,0,0,0, 1, 1.0f);
    // 4) scores = SCALE * Q[b,:,h] @ K[b]^T -> fp32
    gemm_bf3<true, false><<<dim3(SS/BN, SS/BM, BB*HEADS), 256, SMEM_NK>>>(
        qh, ql, kh, kl, sc, nullptr, nullptr,
        HEAD_DIM, HIDDEN, HEAD_DIM, SS,
        SH, HEAD_DIM, SD, 0, (long long)HEADS*SSq, SSq, HEADS, SCALE);
    // 5) softmax -> P pair
    softmax_pair<<<BB*HEADS*SS, 256>>>(sc, ph, pl);
    // 6) attn = P @ V -> pair
    gemm_bf3<false, true><<<dim3(HEAD_DIM/BN, SS/BM, BB*HEADS), 256, SMEM_KN>>>(
        ph, pl, vh, vl, nullptr, ath, atl,
        SS, SS, HEAD_DIM, HIDDEN,
        (long long)HEADS*SSq, SSq, SD, 0, SH, HEAD_DIM, HEADS, 1.0f);
    // 7) out = attn @ Ow^T -> fp32
    gemm_bf3<true, false><<<dim3(HIDDEN/BN, (BB*SS)/BM, 1), 256, SMEM_NK>>>(
        ath, atl, owh, owl, out, nullptr, nullptr,
        HIDDEN, HIDDEN, HIDDEN, HIDDEN, 0,0,0,0,0,0, 1, 1.0f);
}

// round 3
// speedup vs baseline: 3.1380x; 1.1246x over previous
#include <cuda_runtime.h>
#include <cuda_bf16.h>
#include <cstdint>

// ---------------------------------------------------------------------------
// ProductionFastMQA round 3: bf16x3 projection GEMMs (unchanged from R2) +
// fused flash-attention kernel (online softmax, in-register P, no scores
// materialization).
// ---------------------------------------------------------------------------

#define HIDDEN   2048
#define HEADS    16
#define HEAD_DIM 128
#define BB       2
#define SS       2048
#define SCALE    0.08838834764831845f   // 1/sqrt(128)

#define BM   128
#define BN   128
#define BKb  32
#define ASTR (BKb + 8)
#define BSTR_KN (BN + 8)
#define ASZ  (BM * ASTR)
#define BSZ_NK (BN * ASTR)
#define BSZ_KN (BKb * BSTR_KN)
#define SMEM_NK ((4*ASZ + 4*BSZ_NK) * 2)
#define SMEM_KN ((4*ASZ + 4*BSZ_KN) * 2)

// flash tile config
#define TQ 128
#define TK 128
#define DD 128
#define FSTR 136                  // bf16 row stride (272B, conflict-free)
#define FTILE (TQ * FSTR)         // elems per tile
#define FTB   (FTILE * 2)         // bytes per tile
#define FSMEM (6 * FTB)           // Qh Ql Kh Kl Vh Vl = 208896 B

// ----------------------------- scratch -------------------------------------
__device__ __nv_bfloat16 g_xh[BB*SS*HIDDEN],  g_xl[BB*SS*HIDDEN];
__device__ __nv_bfloat16 g_qwh[HIDDEN*HIDDEN], g_qwl[HIDDEN*HIDDEN];
__device__ __nv_bfloat16 g_kwh[HEAD_DIM*HIDDEN], g_kwl[HEAD_DIM*HIDDEN];
__device__ __nv_bfloat16 g_vwh[HEAD_DIM*HIDDEN], g_vwl[HEAD_DIM*HIDDEN];
__device__ __nv_bfloat16 g_owh[HIDDEN*HIDDEN], g_owl[HIDDEN*HIDDEN];
__device__ __nv_bfloat16 g_qh[BB*SS*HIDDEN],  g_ql[BB*SS*HIDDEN];
__device__ __nv_bfloat16 g_kh[BB*SS*HEAD_DIM], g_kl[BB*SS*HEAD_DIM];
__device__ __nv_bfloat16 g_vh[BB*SS*HEAD_DIM], g_vl[BB*SS*HEAD_DIM];
__device__ __nv_bfloat16 g_ath[BB*SS*HIDDEN], g_atl[BB*SS*HIDDEN];

// ----------------------------- PTX helpers ---------------------------------
__device__ __forceinline__ void ldm4(uint32_t* r, uint32_t a) {
    asm volatile("ldmatrix.sync.aligned.m8n8.x4.shared.b16 {%0,%1,%2,%3},[%4];"
                 : "=r"(r[0]), "=r"(r[1]), "=r"(r[2]), "=r"(r[3]) : "r"(a));
}
__device__ __forceinline__ void ldm4t(uint32_t* r, uint32_t a) {
    asm volatile("ldmatrix.sync.aligned.m8n8.x4.trans.shared.b16 {%0,%1,%2,%3},[%4];"
                 : "=r"(r[0]), "=r"(r[1]), "=r"(r[2]), "=r"(r[3]) : "r"(a));
}
__device__ __forceinline__ void cpa16(uint32_t d, const void* s) {
    asm volatile("cp.async.cg.shared.global [%0],[%1],16;" :: "r"(d), "l"(s));
}
__device__ __forceinline__ void mma16(float* c, const uint32_t* a, const uint32_t* b) {
    asm volatile(
        "mma.sync.aligned.m16n8k16.row.col.f32.bf16.bf16.f32 "
        "{%0,%1,%2,%3},{%4,%5,%6,%7},{%8,%9},{%0,%1,%2,%3};"
        : "+f"(c[0]), "+f"(c[1]), "+f"(c[2]), "+f"(c[3])
        : "r"(a[0]), "r"(a[1]), "r"(a[2]), "r"(a[3]), "r"(b[0]), "r"(b[1]));
}
__device__ __forceinline__ void packpair(float a, float b, uint32_t& hi, uint32_t& lo) {
    __nv_bfloat162 H, L;
    H.x = __float2bfloat16(a); H.y = __float2bfloat16(b);
    L.x = __float2bfloat16(a - __bfloat162float(H.x));
    L.y = __float2bfloat16(b - __bfloat162float(H.y));
    hi = *reinterpret_cast<uint32_t*>(&H);
    lo = *reinterpret_cast<uint32_t*>(&L);
}

// ---------------------------------------------------------------------------
// Generic batched/strided bf16x3 GEMM (identical to round 2).
// ---------------------------------------------------------------------------
template <bool B_NK, bool OUT_PAIR>
__global__ __launch_bounds__(256) void gemm_bf3(
    const __nv_bfloat16* __restrict__ Ah, const __nv_bfloat16* __restrict__ Al,
    const __nv_bfloat16* __restrict__ Bh, const __nv_bfloat16* __restrict__ Bl,
    float* __restrict__ C, __nv_bfloat16* __restrict__ Chi, __nv_bfloat16* __restrict__ Clo,
    int K, int lda, int ldb, int ldc,
    long long aB, long long aH, long long bB, long long bH,
    long long cB, long long cH, int hdiv, float alpha)
{
    extern __shared__ __nv_bfloat16 sm[];
    const int BSZ = B_NK ? BSZ_NK : BSZ_KN;
    __nv_bfloat16* Asm = sm;
    __nv_bfloat16* Bsm = sm + 4 * ASZ;
    const uint32_t as_base = (uint32_t)__cvta_generic_to_shared(Asm);
    const uint32_t bs_base = (uint32_t)__cvta_generic_to_shared(Bsm);

    const int z = blockIdx.z;
    const int zb = z / hdiv, zh = z - zb * hdiv;
    Ah += zb * aB + zh * aH;  Al += zb * aB + zh * aH;
    Bh += zb * bB + zh * bH;  Bl += zb * bB + zh * bH;
    const long long coff = zb * cB + zh * cH;

    const int tid = threadIdx.x, lane = tid & 31, warp = tid >> 5;
    const int wm0 = (warp >> 2) * 64;
    const int wn0 = (warp & 3) * 32;
    const int m0 = blockIdx.y * BM, n0 = blockIdx.x * BN;

    float acc[4][4][4] = {};
    const int ar = tid >> 2;
    const int ac = (tid & 3) * 8;

    auto ld_stage = [&](int kt, int st) {
#pragma unroll
        for (int i = 0; i < 2; i++) {
            int r = ar + i * 64;
            long long go = (long long)(m0 + r) * lda + kt + ac;
            uint32_t so = (uint32_t)(r * ASTR + ac) * 2;
            cpa16(as_base + (st*2+0)*ASZ*2 + so, Ah + go);
            cpa16(as_base + (st*2+1)*ASZ*2 + so, Al + go);
        }
        if (B_NK) {
#pragma unroll
            for (int i = 0; i < 2; i++) {
                int r = ar + i * 64;
                long long go = (long long)(n0 + r) * ldb + kt + ac;
                uint32_t so = (uint32_t)(r * ASTR + ac) * 2;
                cpa16(bs_base + (st*2+0)*BSZ_NK*2 + so, Bh + go);
                cpa16(bs_base + (st*2+1)*BSZ_NK*2 + so, Bl + go);
            }
        } else {
#pragma unroll
            for (int i = 0; i < 2; i++) {
                int idx = tid + i * 256;
                int r = idx >> 4, c = (idx & 15) * 8;
                long long go = (long long)(kt + r) * ldb + n0 + c;
                uint32_t so = (uint32_t)(r * BSTR_KN + c) * 2;
                cpa16(bs_base + (st*2+0)*BSZ_KN*2 + so, Bh + go);
                cpa16(bs_base + (st*2+1)*BSZ_KN*2 + so, Bl + go);
            }
        }
    };

    ld_stage(0, 0);
    asm volatile("cp.async.commit_group;");

    const int T = K / BKb;
    for (int t = 0; t < T; t++) {
        if (t + 1 < T) {
            ld_stage((t + 1) * BKb, (t + 1) & 1);
            asm volatile("cp.async.commit_group;");
            asm volatile("cp.async.wait_group 1;");
        } else {
            asm volatile("cp.async.wait_group 0;");
        }
        __syncthreads();
        const int st = t & 1;
        const uint32_t aH0 = as_base + (st*2+0)*ASZ*2;
        const uint32_t aL0 = as_base + (st*2+1)*ASZ*2;
        const uint32_t bH0 = bs_base + (st*2+0)*BSZ*2;
        const uint32_t bL0 = bs_base + (st*2+1)*BSZ*2;

#pragma unroll
        for (int kk = 0; kk < BKb; kk += 16) {
            uint32_t ah[4][4], al[4][4];
            const int arow = wm0 + (lane & 15);
            const int acol = kk + ((lane >> 4) << 3);
#pragma unroll
            for (int mi = 0; mi < 4; mi++) {
                uint32_t off = (uint32_t)((arow + mi*16) * ASTR + acol) * 2;
                ldm4(ah[mi], aH0 + off);
                ldm4(al[mi], aL0 + off);
            }
            uint32_t bh[4][2], bl[4][2];
            if (B_NK) {
                const int br = wn0 + ((lane >> 4) << 3) + (lane & 7);
                const int bc = kk + (((lane >> 3) & 1) << 3);
#pragma unroll
                for (int j = 0; j < 2; j++) {
                    uint32_t off = (uint32_t)((br + j*16) * ASTR + bc) * 2;
                    uint32_t r4[4];
                    ldm4(r4, bH0 + off);
                    bh[2*j][0]=r4[0]; bh[2*j][1]=r4[1]; bh[2*j+1][0]=r4[2]; bh[2*j+1][1]=r4[3];
                    ldm4(r4, bL0 + off);
                    bl[2*j][0]=r4[0]; bl[2*j][1]=r4[1]; bl[2*j+1][0]=r4[2]; bl[2*j+1][1]=r4[3];
                }
            } else {
                const int bk = kk + (((lane >> 3) & 1) << 3) + (lane & 7);
                const int bn = wn0 + ((lane >> 4) << 3);
#pragma unroll
                for (int j = 0; j < 2; j++) {
                    uint32_t off = (uint32_t)(bk * BSTR_KN + bn + j*16) * 2;
                    uint32_t r4[4];
                    ldm4t(r4, bH0 + off);
                    bh[2*j][0]=r4[0]; bh[2*j][1]=r4[1]; bh[2*j+1][0]=r4[2]; bh[2*j+1][1]=r4[3];
                    ldm4t(r4, bL0 + off);
                    bl[2*j][0]=r4[0]; bl[2*j][1]=r4[1]; bl[2*j+1][0]=r4[2]; bl[2*j+1][1]=r4[3];
                }
            }
#pragma unroll
            for (int mi = 0; mi < 4; mi++)
#pragma unroll
                for (int ni = 0; ni < 4; ni++) {
                    mma16(acc[mi][ni], ah[mi], bh[ni]);
                    mma16(acc[mi][ni], ah[mi], bl[ni]);
                    mma16(acc[mi][ni], al[mi], bh[ni]);
                }
        }
        __syncthreads();
    }

    const int lr = lane >> 2, lc = lane & 3;
#pragma unroll
    for (int mi = 0; mi < 4; mi++) {
#pragma unroll
        for (int ni = 0; ni < 4; ni++) {
            const int row = m0 + wm0 + mi*16 + lr;
            const int col = n0 + wn0 + ni*8 + 2*lc;
            if (OUT_PAIR) {
#pragma unroll
                for (int hf = 0; hf < 2; hf++) {
                    float c0 = alpha * acc[mi][ni][2*hf];
                    float c1 = alpha * acc[mi][ni][2*hf + 1];
                    uint32_t hh, ll;
                    packpair(c0, c1, hh, ll);
                    long long o = coff + (long long)(row + 8*hf) * ldc + col;
                    *(uint32_t*)(Chi + o) = hh;
                    *(uint32_t*)(Clo + o) = ll;
                }
            } else {
                long long o = coff + (long long)row * ldc + col;
                *(float2*)(C + o) =
                    make_float2(alpha * acc[mi][ni][0], alpha * acc[mi][ni][1]);
                *(float2*)(C + o + 8LL * ldc) =
                    make_float2(alpha * acc[mi][ni][2], alpha * acc[mi][ni][3]);
            }
        }
    }
}

// ------------------------- fp32 -> bf16 hi/lo split -------------------------
__global__ __launch_bounds__(256) void splitk(
    const float* __restrict__ in, __nv_bfloat16* __restrict__ hi,
    __nv_bfloat16* __restrict__ lo, int n4)
{
    int i = blockIdx.x * 256 + threadIdx.x;
    if (i >= n4) return;
    float4 v = ((const float4*)in)[i];
    uint32_t h0, l0, h1, l1;
    packpair(v.x, v.y, h0, l0);
    packpair(v.z, v.w, h1, l1);
    ((uint32_t*)hi)[2*i]     = h0;
    ((uint32_t*)hi)[2*i + 1] = h1;
    ((uint32_t*)lo)[2*i]     = l0;
    ((uint32_t*)lo)[2*i + 1] = l1;
}

// ---------------------------------------------------------------------------
// Fused flash attention. Q pre-scaled by 1/sqrt(d). One CTA = 128 Q rows of
// one (b,h). 8 warps, 16 Q-rows per warp. Online softmax; P kept in registers
// as bf16 hi/lo A-fragments (FA2 accumulator-reuse layout).
// ---------------------------------------------------------------------------
__global__ __launch_bounds__(256, 1) void flash_attn(
    const __nv_bfloat16* __restrict__ Qh_, const __nv_bfloat16* __restrict__ Ql_,
    const __nv_bfloat16* __restrict__ Kh_, const __nv_bfloat16* __restrict__ Kl_,
    const __nv_bfloat16* __restrict__ Vh_, const __nv_bfloat16* __restrict__ Vl_,
    __nv_bfloat16* __restrict__ Oh_, __nv_bfloat16* __restrict__ Ol_)
{
    extern __shared__ __nv_bfloat16 fsm[];
    const int b = blockIdx.y >> 4, h = blockIdx.y & 15;
    const int q0 = blockIdx.x * TQ;
    const int tid = threadIdx.x, lane = tid & 31, warp = tid >> 5;
    const int lr = lane >> 2, lc = lane & 3;

    const uint32_t s0  = (uint32_t)__cvta_generic_to_shared(fsm);
    const uint32_t sQh = s0,           sQl = s0 + FTB;
    const uint32_t sKh = s0 + 2*FTB,   sKl = s0 + 3*FTB;
    const uint32_t sVh = s0 + 4*FTB,   sVl = s0 + 5*FTB;

    // ---- load Q tile + K(0) ----
#pragma unroll
    for (int i = 0; i < 8; i++) {
        int id = tid + i * 256;
        int r = id >> 4, c = (id & 15) * 8;
        uint32_t so = (uint32_t)(r * FSTR + c) * 2;
        long long gq = (long long)(b * SS + q0 + r) * HIDDEN + h * DD + c;
        cpa16(sQh + so, Qh_ + gq);
        cpa16(sQl + so, Ql_ + gq);
        long long gk = (long long)(b * SS + r) * DD + c;
        cpa16(sKh + so, Kh_ + gk);
        cpa16(sKl + so, Kl_ + gk);
    }
    asm volatile("cp.async.commit_group;");
    asm volatile("cp.async.wait_group 0;");
    __syncthreads();

    float oacc[16][4] = {};
    float mrow[2] = {-1e30f, -1e30f};
    float lrow[2] = {0.f, 0.f};

    for (int t = 0; t < SS / TK; t++) {
        // prefetch V(t) under S-compute
#pragma unroll
        for (int i = 0; i < 8; i++) {
            int id = tid + i * 256;
            int r = id >> 4, c = (id & 15) * 8;
            uint32_t so = (uint32_t)(r * FSTR + c) * 2;
            long long gv = (long long)(b * SS + t * TK + r) * DD + c;
            cpa16(sVh + so, Vh_ + gv);
            cpa16(sVl + so, Vl_ + gv);
        }
        asm volatile("cp.async.commit_group;");

        // ---- S = Q K^T (bf16x3) ----
        float sacc[16][4] = {};
#pragma unroll
        for (int kk = 0; kk < 8; kk++) {
            uint32_t qh4[4], ql4[4];
            uint32_t aoff = (uint32_t)((warp*16 + (lane & 15)) * FSTR
                                       + kk*16 + ((lane >> 4) << 3)) * 2;
            ldm4(qh4, sQh + aoff);
            ldm4(ql4, sQl + aoff);
#pragma unroll
            for (int j = 0; j < 8; j++) {
                uint32_t boff = (uint32_t)((j*16 + ((lane >> 4) << 3) + (lane & 7)) * FSTR
                                           + kk*16 + (((lane >> 3) & 1) << 3)) * 2;
                uint32_t kh4[4], kl4[4];
                ldm4(kh4, sKh + boff);
                ldm4(kl4, sKl + boff);
                mma16(sacc[2*j],   qh4, kh4);     mma16(sacc[2*j],   ql4, kh4);
                mma16(sacc[2*j],   qh4, kl4);
                mma16(sacc[2*j+1], qh4, kh4 + 2); mma16(sacc[2*j+1], ql4, kh4 + 2);
                mma16(sacc[2*j+1], qh4, kl4 + 2);
            }
        }

        // ---- online softmax (registers only) ----
        float tm0 = -1e30f, tm1 = -1e30f;
#pragma unroll
        for (int ni = 0; ni < 16; ni++) {
            tm0 = fmaxf(tm0, fmaxf(sacc[ni][0], sacc[ni][1]));
            tm1 = fmaxf(tm1, fmaxf(sacc[ni][2], sacc[ni][3]));
        }
        tm0 = fmaxf(tm0, __shfl_xor_sync(0xffffffffu, tm0, 1));
        tm0 = fmaxf(tm0, __shfl_xor_sync(0xffffffffu, tm0, 2));
        tm1 = fmaxf(tm1, __shfl_xor_sync(0xffffffffu, tm1, 1));
        tm1 = fmaxf(tm1, __shfl_xor_sync(0xffffffffu, tm1, 2));
        float mn0 = fmaxf(mrow[0], tm0), mn1 = fmaxf(mrow[1], tm1);
        float f0 = __expf(mrow[0] - mn0), f1 = __expf(mrow[1] - mn1);
        mrow[0] = mn0; mrow[1] = mn1;
        float s0a = 0.f, s1a = 0.f;
#pragma unroll
        for (int ni = 0; ni < 16; ni++) {
            sacc[ni][0] = __expf(sacc[ni][0] - mn0);
            sacc[ni][1] = __expf(sacc[ni][1] - mn0);
            sacc[ni][2] = __expf(sacc[ni][2] - mn1);
            sacc[ni][3] = __expf(sacc[ni][3] - mn1);
            s0a += sacc[ni][0] + sacc[ni][1];
            s1a += sacc[ni][2] + sacc[ni][3];
        }
        s0a += __shfl_xor_sync(0xffffffffu, s0a, 1);
        s0a += __shfl_xor_sync(0xffffffffu, s0a, 2);
        s1a += __shfl_xor_sync(0xffffffffu, s1a, 1);
        s1a += __shfl_xor_sync(0xffffffffu, s1a, 2);
        lrow[0] = lrow[0] * f0 + s0a;
        lrow[1] = lrow[1] * f1 + s1a;
#pragma unroll
        for (int nd = 0; nd < 16; nd++) {
            oacc[nd][0] *= f0; oacc[nd][1] *= f0;
            oacc[nd][2] *= f1; oacc[nd][3] *= f1;
        }

        // V(t) ready; all warps done reading K(t)
        asm volatile("cp.async.wait_group 0;");
        __syncthreads();

        // prefetch K(t+1) under PV-compute
        if (t + 1 < SS / TK) {
#pragma unroll
            for (int i = 0; i < 8; i++) {
                int id = tid + i * 256;
                int r = id >> 4, c = (id & 15) * 8;
                uint32_t so = (uint32_t)(r * FSTR + c) * 2;
                long long gk = (long long)(b * SS + (t + 1) * TK + r) * DD + c;
                cpa16(sKh + so, Kh_ + gk);
                cpa16(sKl + so, Kl_ + gk);
            }
            asm volatile("cp.async.commit_group;");
        }

        // ---- O += P V (P in registers, hi/lo) ----
#pragma unroll
        for (int c = 0; c < 8; c++) {
            uint32_t ph4[4], pl4[4];
            packpair(sacc[2*c][0],   sacc[2*c][1],   ph4[0], pl4[0]);
            packpair(sacc[2*c][2],   sacc[2*c][3],   ph4[1], pl4[1]);
            packpair(sacc[2*c+1][0], sacc[2*c+1][1], ph4[2], pl4[2]);
            packpair(sacc[2*c+1][2], sacc[2*c+1][3], ph4[3], pl4[3]);
#pragma unroll
            for (int j = 0; j < 8; j++) {
                uint32_t boff = (uint32_t)((c*16 + (((lane >> 3) & 1) << 3) + (lane & 7)) * FSTR
                                           + j*16 + ((lane >> 4) << 3)) * 2;
                uint32_t vh4[4], vl4[4];
                ldm4t(vh4, sVh + boff);
                ldm4t(vl4, sVl + boff);
                mma16(oacc[2*j],   ph4, vh4);     mma16(oacc[2*j],   pl4, vh4);
                mma16(oacc[2*j],   ph4, vl4);
                mma16(oacc[2*j+1], ph4, vh4 + 2); mma16(oacc[2*j+1], pl4, vh4 + 2);
                mma16(oacc[2*j+1], ph4, vl4 + 2);
            }
        }
        asm volatile("cp.async.wait_group 0;");
        __syncthreads();
    }

    // ---- epilogue: O /= l, write bf16 hi/lo pair ----
    const float i0 = 1.f / lrow[0], i1 = 1.f / lrow[1];
    const long long orow0 = (long long)(b * SS + q0 + warp*16 + lr) * HIDDEN + h * DD;
    const long long orow1 = orow0 + 8LL * HIDDEN;
#pragma unroll
    for (int nd = 0; nd < 16; nd++) {
        const int col = nd * 8 + 2 * lc;
        uint32_t hh, ll;
        packpair(oacc[nd][0] * i0, oacc[nd][1] * i0, hh, ll);
        *(uint32_t*)(Oh_ + orow0 + col) = hh;
        *(uint32_t*)(Ol_ + orow0 + col) = ll;
        packpair(oacc[nd][2] * i1, oacc[nd][3] * i1, hh, ll);
        *(uint32_t*)(Oh_ + orow1 + col) = hh;
        *(uint32_t*)(Ol_ + orow1 + col) = ll;
    }
}

// ---------------------------------------------------------------------------

extern "C" void kernel_launch(void* const* d_in, const int* in_sizes, int n_in,
                              void* d_out, int out_size) {
    const float* x  = (const float*)d_in[0];
    const float* qw = (const float*)d_in[1];
    const float* kw = (const float*)d_in[2];
    const float* vw = (const float*)d_in[3];
    const float* ow = (const float*)d_in[4];
    float* out = (float*)d_out;

    __nv_bfloat16 *xh,*xl,*qwh,*qwl,*kwh,*kwl,*vwh,*vwl,*owh,*owl;
    __nv_bfloat16 *qh,*ql,*kh,*kl,*vh,*vl,*ath,*atl;
    cudaGetSymbolAddress((void**)&xh,  g_xh);  cudaGetSymbolAddress((void**)&xl,  g_xl);
    cudaGetSymbolAddress((void**)&qwh, g_qwh); cudaGetSymbolAddress((void**)&qwl, g_qwl);
    cudaGetSymbolAddress((void**)&kwh, g_kwh); cudaGetSymbolAddress((void**)&kwl, g_kwl);
    cudaGetSymbolAddress((void**)&vwh, g_vwh); cudaGetSymbolAddress((void**)&vwl, g_vwl);
    cudaGetSymbolAddress((void**)&owh, g_owh); cudaGetSymbolAddress((void**)&owl, g_owl);
    cudaGetSymbolAddress((void**)&qh,  g_qh);  cudaGetSymbolAddress((void**)&ql,  g_ql);
    cudaGetSymbolAddress((void**)&kh,  g_kh);  cudaGetSymbolAddress((void**)&kl,  g_kl);
    cudaGetSymbolAddress((void**)&vh,  g_vh);  cudaGetSymbolAddress((void**)&vl,  g_vl);
    cudaGetSymbolAddress((void**)&ath, g_ath); cudaGetSymbolAddress((void**)&atl, g_atl);

    cudaFuncSetAttribute((const void*)gemm_bf3<true,  true >,
                         cudaFuncAttributeMaxDynamicSharedMemorySize, SMEM_NK);
    cudaFuncSetAttribute((const void*)gemm_bf3<true,  false>,
                         cudaFuncAttributeMaxDynamicSharedMemorySize, SMEM_NK);
    cudaFuncSetAttribute((const void*)flash_attn,
                         cudaFuncAttributeMaxDynamicSharedMemorySize, FSMEM);

    // 0) splits
    splitk<<<(BB*SS*HIDDEN/4 + 255)/256, 256>>>(x,  xh,  xl,  BB*SS*HIDDEN/4);
    splitk<<<(HIDDEN*HIDDEN/4 + 255)/256, 256>>>(qw, qwh, qwl, HIDDEN*HIDDEN/4);
    splitk<<<(HEAD_DIM*HIDDEN/4 + 255)/256, 256>>>(kw, kwh, kwl, HEAD_DIM*HIDDEN/4);
    splitk<<<(HEAD_DIM*HIDDEN/4 + 255)/256, 256>>>(vw, vwh, vwl, HEAD_DIM*HIDDEN/4);
    splitk<<<(HIDDEN*HIDDEN/4 + 255)/256, 256>>>(ow, owh, owl, HIDDEN*HIDDEN/4);

    // 1) Q = SCALE * X @ Qw^T  -> pair (pre-scaled for attention)
    gemm_bf3<true, true><<<dim3(HIDDEN/BN, (BB*SS)/BM, 1), 256, SMEM_NK>>>(
        xh, xl, qwh, qwl, nullptr, qh, ql,
        HIDDEN, HIDDEN, HIDDEN, HIDDEN, 0,0,0,0,0,0, 1, SCALE);
    // 2) K = X @ Kw^T  -> pair
    gemm_bf3<true, true><<<dim3(HEAD_DIM/BN, (BB*SS)/BM, 1), 256, SMEM_NK>>>(
        xh, xl, kwh, kwl, nullptr, kh, kl,
        HIDDEN, HIDDEN, HIDDEN, HEAD_DIM, 0,0,0,0,0,0, 1, 1.0f);
    // 3) V = X @ Vw^T  -> pair
    gemm_bf3<true, true><<<dim3(HEAD_DIM/BN, (BB*SS)/BM, 1), 256, SMEM_NK>>>(
        xh, xl, vwh, vwl, nullptr, vh, vl,
        HIDDEN, HIDDEN, HIDDEN, HEAD_DIM, 0,0,0,0,0,0, 1, 1.0f);
    // 4) fused attention -> attn pair
    flash_attn<<<dim3(SS/TQ, BB*HEADS), 256, FSMEM>>>(
        qh, ql, kh, kl, vh, vl, ath, atl);
    // 5) out = attn @ Ow^T -> fp32
    gemm_bf3<true, false><<<dim3(HIDDEN/BN, (BB*SS)/BM, 1), 256, SMEM_NK>>>(
        ath, atl, owh, owl, out, nullptr, nullptr,
        HIDDEN, HIDDEN, HIDDEN, HIDDEN, 0,0,0,0,0,0, 1, 1.0f);
}

// round 5
// speedup vs baseline: 3.5752x; 1.1393x over previous
#include <cuda_runtime.h>
#include <cuda_bf16.h>
#include <cstdint>

// ---------------------------------------------------------------------------
// ProductionFastMQA round 5 (mma.sync path — tcgen05 unavailable on this
// build target):
//   * fused QKV projection GEMM (N=2304, SCALE folded into Qw)
//   * gemm launch_bounds(256,2) for 2-CTA/SM occupancy
//   * flash attention: Q in registers, double-buffered K, FIFO-overlapped
//     cp.async pipeline
// ---------------------------------------------------------------------------

#define HIDDEN   2048
#define HEADS    16
#define HEAD_DIM 128
#define BB       2
#define SS       2048
#define SCALE    0.08838834764831845f   // 1/sqrt(128)
#define NQKV     2304                   // 2048 (Q) + 128 (K) + 128 (V)
#define KVLD     256                    // combined KV row stride

// gemm tiles
#define BM   128
#define BN   128
#define BKb  32
#define ASTR (BKb + 8)          // 40
#define ASZ  (BM * ASTR)        // 5120
#define SMEM_NK ((8 * ASZ) * 2) // 81920 B (2 stages x (Ah,Al,Bh,Bl))

// flash tiles
#define TQ 128
#define TK 128
#define DD 128
#define FSTR 136
#define FTB  (TQ * FSTR * 2)    // 34816 B per tile
#define FSMEM (6 * FTB)         // K0h K0l K1h K1l Vh Vl = 208896 B

// ----------------------------- scratch -------------------------------------
__device__ __nv_bfloat16 g_xh[BB*SS*HIDDEN],  g_xl[BB*SS*HIDDEN];
__device__ __nv_bfloat16 g_wh[NQKV*HIDDEN],   g_wl[NQKV*HIDDEN];   // QKV weights
__device__ __nv_bfloat16 g_owh[HIDDEN*HIDDEN], g_owl[HIDDEN*HIDDEN];
__device__ __nv_bfloat16 g_qh[BB*SS*HIDDEN],  g_ql[BB*SS*HIDDEN];
__device__ __nv_bfloat16 g_kvh[BB*SS*KVLD],   g_kvl[BB*SS*KVLD];   // K|V combined
__device__ __nv_bfloat16 g_ath[BB*SS*HIDDEN], g_atl[BB*SS*HIDDEN];

// ----------------------------- PTX helpers ---------------------------------
__device__ __forceinline__ uint32_t smem_u32(const void* p) {
    uint32_t a;
    asm("{ .reg .u64 t; cvta.to.shared.u64 t, %1; cvt.u32.u64 %0, t; }"
        : "=r"(a) : "l"(p));
    return a;
}
__device__ __forceinline__ void ldm4(uint32_t* r, uint32_t a) {
    asm volatile("ldmatrix.sync.aligned.m8n8.x4.shared.b16 {%0,%1,%2,%3},[%4];"
                 : "=r"(r[0]), "=r"(r[1]), "=r"(r[2]), "=r"(r[3]) : "r"(a));
}
__device__ __forceinline__ void ldm4t(uint32_t* r, uint32_t a) {
    asm volatile("ldmatrix.sync.aligned.m8n8.x4.trans.shared.b16 {%0,%1,%2,%3},[%4];"
                 : "=r"(r[0]), "=r"(r[1]), "=r"(r[2]), "=r"(r[3]) : "r"(a));
}
__device__ __forceinline__ void cpa16(uint32_t d, const void* s) {
    asm volatile("cp.async.cg.shared.global [%0],[%1],16;" :: "r"(d), "l"(s));
}
__device__ __forceinline__ void mma16(float* c, const uint32_t* a, const uint32_t* b) {
    asm volatile(
        "mma.sync.aligned.m16n8k16.row.col.f32.bf16.bf16.f32 "
        "{%0,%1,%2,%3},{%4,%5,%6,%7},{%8,%9},{%0,%1,%2,%3};"
        : "+f"(c[0]), "+f"(c[1]), "+f"(c[2]), "+f"(c[3])
        : "r"(a[0]), "r"(a[1]), "r"(a[2]), "r"(a[3]), "r"(b[0]), "r"(b[1]));
}
__device__ __forceinline__ void packpair(float a, float b, uint32_t& hi, uint32_t& lo) {
    __nv_bfloat162 H, L;
    H.x = __float2bfloat16(a); H.y = __float2bfloat16(b);
    L.x = __float2bfloat16(a - __bfloat162float(H.x));
    L.y = __float2bfloat16(b - __bfloat162float(H.y));
    hi = *reinterpret_cast<uint32_t*>(&H);
    lo = *reinterpret_cast<uint32_t*>(&L);
}

// ---------------------------------------------------------------------------
// bf16x3 GEMM, A [4096,2048] pair, B [N,2048] pair row-major (C = A B^T).
// MODE 0: QKV — bf16 pair outputs routed Q (cols<2048) / KV (cols>=2048)
// MODE 1: fp32 output, ldc=2048 (O-projection)
// ---------------------------------------------------------------------------
template <int MODE>
__global__ __launch_bounds__(256, 2) void gemm_bf3(
    const __nv_bfloat16* __restrict__ Ah, const __nv_bfloat16* __restrict__ Al,
    const __nv_bfloat16* __restrict__ Bh, const __nv_bfloat16* __restrict__ Bl,
    __nv_bfloat16* __restrict__ Qhi, __nv_bfloat16* __restrict__ Qlo,
    __nv_bfloat16* __restrict__ KVhi, __nv_bfloat16* __restrict__ KVlo,
    float* __restrict__ Cf)
{
    extern __shared__ __nv_bfloat16 sm[];
    const uint32_t as_base = smem_u32(sm);
    const uint32_t bs_base = as_base + 4 * ASZ * 2;

    const int tid = threadIdx.x, lane = tid & 31, warp = tid >> 5;
    const int wm0 = (warp >> 2) * 64;
    const int wn0 = (warp & 3) * 32;
    const int m0 = blockIdx.y * BM, n0 = blockIdx.x * BN;

    float acc[4][4][4] = {};
    const int ar = tid >> 2;
    const int ac = (tid & 3) * 8;

    auto ld_stage = [&](int kt, int st) {
#pragma unroll
        for (int i = 0; i < 2; i++) {
            int r = ar + i * 64;
            long long go = (long long)(m0 + r) * HIDDEN + kt + ac;
            uint32_t so = (uint32_t)(r * ASTR + ac) * 2;
            cpa16(as_base + (st*2+0)*ASZ*2 + so, Ah + go);
            cpa16(as_base + (st*2+1)*ASZ*2 + so, Al + go);
            long long gb = (long long)(n0 + r) * HIDDEN + kt + ac;
            cpa16(bs_base + (st*2+0)*ASZ*2 + so, Bh + gb);
            cpa16(bs_base + (st*2+1)*ASZ*2 + so, Bl + gb);
        }
    };

    ld_stage(0, 0);
    asm volatile("cp.async.commit_group;");

    const int T = HIDDEN / BKb;
    for (int t = 0; t < T; t++) {
        if (t + 1 < T) {
            ld_stage((t + 1) * BKb, (t + 1) & 1);
            asm volatile("cp.async.commit_group;");
            asm volatile("cp.async.wait_group 1;");
        } else {
            asm volatile("cp.async.wait_group 0;");
        }
        __syncthreads();
        const int st = t & 1;
        const uint32_t aH0 = as_base + (st*2+0)*ASZ*2;
        const uint32_t aL0 = as_base + (st*2+1)*ASZ*2;
        const uint32_t bH0 = bs_base + (st*2+0)*ASZ*2;
        const uint32_t bL0 = bs_base + (st*2+1)*ASZ*2;

#pragma unroll
        for (int kk = 0; kk < BKb; kk += 16) {
            uint32_t ah[4][4], al[4][4];
            const int arow = wm0 + (lane & 15);
            const int acol = kk + ((lane >> 4) << 3);
#pragma unroll
            for (int mi = 0; mi < 4; mi++) {
                uint32_t off = (uint32_t)((arow + mi*16) * ASTR + acol) * 2;
                ldm4(ah[mi], aH0 + off);
                ldm4(al[mi], aL0 + off);
            }
            uint32_t bh[4][2], bl[4][2];
            const int br = wn0 + ((lane >> 4) << 3) + (lane & 7);
            const int bc = kk + (((lane >> 3) & 1) << 3);
#pragma unroll
            for (int j = 0; j < 2; j++) {
                uint32_t off = (uint32_t)((br + j*16) * ASTR + bc) * 2;
                uint32_t r4[4];
                ldm4(r4, bH0 + off);
                bh[2*j][0]=r4[0]; bh[2*j][1]=r4[1]; bh[2*j+1][0]=r4[2]; bh[2*j+1][1]=r4[3];
                ldm4(r4, bL0 + off);
                bl[2*j][0]=r4[0]; bl[2*j][1]=r4[1]; bl[2*j+1][0]=r4[2]; bl[2*j+1][1]=r4[3];
            }
#pragma unroll
            for (int mi = 0; mi < 4; mi++)
#pragma unroll
                for (int ni = 0; ni < 4; ni++) {
                    mma16(acc[mi][ni], ah[mi], bh[ni]);
                    mma16(acc[mi][ni], ah[mi], bl[ni]);
                    mma16(acc[mi][ni], al[mi], bh[ni]);
                }
        }
        __syncthreads();
    }

    const int lr = lane >> 2, lc = lane & 3;
    if (MODE == 0) {
        const bool isQ = (n0 < HIDDEN);
        __nv_bfloat16* Oh = isQ ? Qhi : KVhi;
        __nv_bfloat16* Ol = isQ ? Qlo : KVlo;
        const int ldc = isQ ? HIDDEN : KVLD;
        const int cb  = isQ ? n0 : (n0 - HIDDEN);
#pragma unroll
        for (int mi = 0; mi < 4; mi++)
#pragma unroll
            for (int ni = 0; ni < 4; ni++) {
                const int row = m0 + wm0 + mi*16 + lr;
                const int col = cb + wn0 + ni*8 + 2*lc;
#pragma unroll
                for (int hf = 0; hf < 2; hf++) {
                    uint32_t hh, ll;
                    packpair(acc[mi][ni][2*hf], acc[mi][ni][2*hf + 1], hh, ll);
                    long long o = (long long)(row + 8*hf) * ldc + col;
                    *(uint32_t*)(Oh + o) = hh;
                    *(uint32_t*)(Ol + o) = ll;
                }
            }
    } else {
#pragma unroll
        for (int mi = 0; mi < 4; mi++)
#pragma unroll
            for (int ni = 0; ni < 4; ni++) {
                const int row = m0 + wm0 + mi*16 + lr;
                const int col = n0 + wn0 + ni*8 + 2*lc;
                long long o = (long long)row * HIDDEN + col;
                *(float2*)(Cf + o) = make_float2(acc[mi][ni][0], acc[mi][ni][1]);
                *(float2*)(Cf + o + 8LL * HIDDEN) =
                    make_float2(acc[mi][ni][2], acc[mi][ni][3]);
            }
    }
}

// ------------------------- split kernels ------------------------------------
__global__ __launch_bounds__(256) void splitk(
    const float* __restrict__ in, __nv_bfloat16* __restrict__ hi,
    __nv_bfloat16* __restrict__ lo, int n4)
{
    int i = blockIdx.x * 256 + threadIdx.x;
    if (i >= n4) return;
    float4 v = ((const float4*)in)[i];
    uint32_t h0, l0, h1, l1;
    packpair(v.x, v.y, h0, l0);
    packpair(v.z, v.w, h1, l1);
    ((uint32_t*)hi)[2*i]     = h0;
    ((uint32_t*)hi)[2*i + 1] = h1;
    ((uint32_t*)lo)[2*i]     = l0;
    ((uint32_t*)lo)[2*i + 1] = l1;
}

// pack [Qw*SCALE ; Kw ; Vw] -> combined [2304,2048] hi/lo
__global__ __launch_bounds__(256) void splitw_qkv(
    const float* __restrict__ qw, const float* __restrict__ kw,
    const float* __restrict__ vw, __nv_bfloat16* __restrict__ wh,
    __nv_bfloat16* __restrict__ wl)
{
    int i = blockIdx.x * 256 + threadIdx.x;            // float4 index
    if (i >= NQKV * HIDDEN / 4) return;
    long long e = (long long)i * 4;
    int r = (int)(e >> 11);
    int c = (int)(e & 2047);
    const float* src;
    float sc = 1.0f;
    if (r < 2048)      { src = qw + ((long long)r << 11) + c; sc = SCALE; }
    else if (r < 2176) { src = kw + ((long long)(r - 2048) << 11) + c; }
    else               { src = vw + ((long long)(r - 2176) << 11) + c; }
    float4 v = *(const float4*)src;
    uint32_t h0, l0, h1, l1;
    packpair(v.x * sc, v.y * sc, h0, l0);
    packpair(v.z * sc, v.w * sc, h1, l1);
    ((uint32_t*)wh)[2*i]     = h0;
    ((uint32_t*)wh)[2*i + 1] = h1;
    ((uint32_t*)wl)[2*i]     = l0;
    ((uint32_t*)wl)[2*i + 1] = l1;
}

// ---------------------------------------------------------------------------
// Flash attention: Q fragments in registers (loop-invariant), double-buffered
// K, single V buffer. K/V read from combined [B*S, 256] (K cols 0-127, V
// cols 128-255). cp.async FIFO: K(t+1) overlaps PV, V(t) overlaps S.
// ---------------------------------------------------------------------------
__global__ __launch_bounds__(256, 1) void flash_attn(
    const __nv_bfloat16* __restrict__ Qh_, const __nv_bfloat16* __restrict__ Ql_,
    const __nv_bfloat16* __restrict__ KVh_, const __nv_bfloat16* __restrict__ KVl_,
    __nv_bfloat16* __restrict__ Oh_, __nv_bfloat16* __restrict__ Ol_)
{
    extern __shared__ __nv_bfloat16 fsm[];
    const int b = blockIdx.y >> 4, h = blockIdx.y & 15;
    const int q0 = blockIdx.x * TQ;
    const int tid = threadIdx.x, lane = tid & 31, warp = tid >> 5;
    const int lr = lane >> 2, lc = lane & 3;

    const uint32_t s0 = smem_u32(fsm);
    // tiles: [K0h][K0l][K1h][K1l][Vh][Vl]
    const uint32_t sVh = s0 + 4*FTB, sVl = s0 + 5*FTB;

    // ---- stage Q into V buffers, move to registers ----
#pragma unroll
    for (int i = 0; i < 8; i++) {
        int id = tid + i * 256;
        int r = id >> 4, c = (id & 15) * 8;
        uint32_t so = (uint32_t)(r * FSTR + c) * 2;
        long long gq = (long long)(b * SS + q0 + r) * HIDDEN + h * DD + c;
        cpa16(sVh + so, Qh_ + gq);
        cpa16(sVl + so, Ql_ + gq);
    }
    asm volatile("cp.async.commit_group;");
    asm volatile("cp.async.wait_group 0;");
    __syncthreads();

    uint32_t qhr[8][4], qlr[8][4];
#pragma unroll
    for (int kk = 0; kk < 8; kk++) {
        uint32_t aoff = (uint32_t)((warp*16 + (lane & 15)) * FSTR
                                   + kk*16 + ((lane >> 4) << 3)) * 2;
        ldm4(qhr[kk], sVh + aoff);
        ldm4(qlr[kk], sVl + aoff);
    }
    __syncthreads();

    // ---- K(0) prefetch ----
#pragma unroll
    for (int i = 0; i < 8; i++) {
        int id = tid + i * 256;
        int r = id >> 4, c = (id & 15) * 8;
        uint32_t so = (uint32_t)(r * FSTR + c) * 2;
        long long gk = (long long)(b * SS + r) * KVLD + c;
        cpa16(s0 + so, KVh_ + gk);
        cpa16(s0 + FTB + so, KVl_ + gk);
    }
    asm volatile("cp.async.commit_group;");      // pending: {K0}

    float oacc[16][4] = {};
    float mrow[2] = {-1e30f, -1e30f};
    float lrow[2] = {0.f, 0.f};

    for (int t = 0; t < SS / TK; t++) {
        const uint32_t sKh = s0 + ((t & 1) ? 2 : 0) * FTB;
        const uint32_t sKl = sKh + FTB;

        // V(t) prefetch (overlaps S)
#pragma unroll
        for (int i = 0; i < 8; i++) {
            int id = tid + i * 256;
            int r = id >> 4, c = (id & 15) * 8;
            uint32_t so = (uint32_t)(r * FSTR + c) * 2;
            long long gv = (long long)(b * SS + t * TK + r) * KVLD + 128 + c;
            cpa16(sVh + so, KVh_ + gv);
            cpa16(sVl + so, KVl_ + gv);
        }
        asm volatile("cp.async.commit_group;");  // pending: {K(t), V(t)}
        asm volatile("cp.async.wait_group 1;");  // K(t) landed
        __syncthreads();

        // ---- S = Q K^T ----
        float sacc[16][4] = {};
#pragma unroll
        for (int kk = 0; kk < 8; kk++) {
#pragma unroll
            for (int j = 0; j < 8; j++) {
                uint32_t boff = (uint32_t)((j*16 + ((lane >> 4) << 3) + (lane & 7)) * FSTR
                                           + kk*16 + (((lane >> 3) & 1) << 3)) * 2;
                uint32_t kh4[4], kl4[4];
                ldm4(kh4, sKh + boff);
                ldm4(kl4, sKl + boff);
                mma16(sacc[2*j],   qhr[kk], kh4);     mma16(sacc[2*j],   qlr[kk], kh4);
                mma16(sacc[2*j],   qhr[kk], kl4);
                mma16(sacc[2*j+1], qhr[kk], kh4 + 2); mma16(sacc[2*j+1], qlr[kk], kh4 + 2);
                mma16(sacc[2*j+1], qhr[kk], kl4 + 2);
            }
        }

        // ---- online softmax ----
        float tm0 = -1e30f, tm1 = -1e30f;
#pragma unroll
        for (int ni = 0; ni < 16; ni++) {
            tm0 = fmaxf(tm0, fmaxf(sacc[ni][0], sacc[ni][1]));
            tm1 = fmaxf(tm1, fmaxf(sacc[ni][2], sacc[ni][3]));
        }
        tm0 = fmaxf(tm0, __shfl_xor_sync(0xffffffffu, tm0, 1));
        tm0 = fmaxf(tm0, __shfl_xor_sync(0xffffffffu, tm0, 2));
        tm1 = fmaxf(tm1, __shfl_xor_sync(0xffffffffu, tm1, 1));
        tm1 = fmaxf(tm1, __shfl_xor_sync(0xffffffffu, tm1, 2));
        float mn0 = fmaxf(mrow[0], tm0), mn1 = fmaxf(mrow[1], tm1);
        float f0 = __expf(mrow[0] - mn0), f1 = __expf(mrow[1] - mn1);
        mrow[0] = mn0; mrow[1] = mn1;
        float s0a = 0.f, s1a = 0.f;
#pragma unroll
        for (int ni = 0; ni < 16; ni++) {
            sacc[ni][0] = __expf(sacc[ni][0] - mn0);
            sacc[ni][1] = __expf(sacc[ni][1] - mn0);
            sacc[ni][2] = __expf(sacc[ni][2] - mn1);
            sacc[ni][3] = __expf(sacc[ni][3] - mn1);
            s0a += sacc[ni][0] + sacc[ni][1];
            s1a += sacc[ni][2] + sacc[ni][3];
        }
        s0a += __shfl_xor_sync(0xffffffffu, s0a, 1);
        s0a += __shfl_xor_sync(0xffffffffu, s0a, 2);
        s1a += __shfl_xor_sync(0xffffffffu, s1a, 1);
        s1a += __shfl_xor_sync(0xffffffffu, s1a, 2);
        lrow[0] = lrow[0] * f0 + s0a;
        lrow[1] = lrow[1] * f1 + s1a;
#pragma unroll
        for (int nd = 0; nd < 16; nd++) {
            oacc[nd][0] *= f0; oacc[nd][1] *= f0;
            oacc[nd][2] *= f1; oacc[nd][3] *= f1;
        }

        // K(t+1) prefetch into other buffer (overlaps PV)
        if (t + 1 < SS / TK) {
            const uint32_t dKh = s0 + (((t + 1) & 1) ? 2 : 0) * FTB;
#pragma unroll
            for (int i = 0; i < 8; i++) {
                int id = tid + i * 256;
                int r = id >> 4, c = (id & 15) * 8;
                uint32_t so = (uint32_t)(r * FSTR + c) * 2;
                long long gk = (long long)(b * SS + (t + 1) * TK + r) * KVLD + c;
                cpa16(dKh + so, KVh_ + gk);
                cpa16(dKh + FTB + so, KVl_ + gk);
            }
            asm volatile("cp.async.commit_group;"); // pending: {V(t), K(t+1)}
            asm volatile("cp.async.wait_group 1;"); // V(t) landed, K(t+1) flies
        } else {
            asm volatile("cp.async.wait_group 0;");
        }
        __syncthreads();

        // ---- O += P V ----
#pragma unroll
        for (int c = 0; c < 8; c++) {
            uint32_t ph4[4], pl4[4];
            packpair(sacc[2*c][0],   sacc[2*c][1],   ph4[0], pl4[0]);
            packpair(sacc[2*c][2],   sacc[2*c][3],   ph4[1], pl4[1]);
            packpair(sacc[2*c+1][0], sacc[2*c+1][1], ph4[2], pl4[2]);
            packpair(sacc[2*c+1][2], sacc[2*c+1][3], ph4[3], pl4[3]);
#pragma unroll
            for (int j = 0; j < 8; j++) {
                uint32_t boff = (uint32_t)((c*16 + (((lane >> 3) & 1) << 3) + (lane & 7)) * FSTR
                                           + j*16 + ((lane >> 4) << 3)) * 2;
                uint32_t vh4[4], vl4[4];
                ldm4t(vh4, sVh + boff);
                ldm4t(vl4, sVl + boff);
                mma16(oacc[2*j],   ph4, vh4);     mma16(oacc[2*j],   pl4, vh4);
                mma16(oacc[2*j],   ph4, vl4);
                mma16(oacc[2*j+1], ph4, vh4 + 2); mma16(oacc[2*j+1], pl4, vh4 + 2);
                mma16(oacc[2*j+1], ph4, vl4 + 2);
            }
        }
        __syncthreads();   // V consumed by all warps before next overwrite
    }

    // ---- epilogue ----
    const float i0 = 1.f / lrow[0], i1 = 1.f / lrow[1];
    const long long orow0 = (long long)(b * SS + q0 + warp*16 + lr) * HIDDEN + h * DD;
    const long long orow1 = orow0 + 8LL * HIDDEN;
#pragma unroll
    for (int nd = 0; nd < 16; nd++) {
        const int col = nd * 8 + 2 * lc;
        uint32_t hh, ll;
        packpair(oacc[nd][0] * i0, oacc[nd][1] * i0, hh, ll);
        *(uint32_t*)(Oh_ + orow0 + col) = hh;
        *(uint32_t*)(Ol_ + orow0 + col) = ll;
        packpair(oacc[nd][2] * i1, oacc[nd][3] * i1, hh, ll);
        *(uint32_t*)(Oh_ + orow1 + col) = hh;
        *(uint32_t*)(Ol_ + orow1 + col) = ll;
    }
}

// ---------------------------------------------------------------------------

extern "C" void kernel_launch(void* const* d_in, const int* in_sizes, int n_in,
                              void* d_out, int out_size) {
    const float* x  = (const float*)d_in[0];
    const float* qw = (const float*)d_in[1];
    const float* kw = (const float*)d_in[2];
    const float* vw = (const float*)d_in[3];
    const float* ow = (const float*)d_in[4];
    float* out = (float*)d_out;

    __nv_bfloat16 *xh,*xl,*wh,*wl,*owh,*owl,*qh,*ql,*kvh,*kvl,*ath,*atl;
    cudaGetSymbolAddress((void**)&xh,  g_xh);  cudaGetSymbolAddress((void**)&xl,  g_xl);
    cudaGetSymbolAddress((void**)&wh,  g_wh);  cudaGetSymbolAddress((void**)&wl,  g_wl);
    cudaGetSymbolAddress((void**)&owh, g_owh); cudaGetSymbolAddress((void**)&owl, g_owl);
    cudaGetSymbolAddress((void**)&qh,  g_qh);  cudaGetSymbolAddress((void**)&ql,  g_ql);
    cudaGetSymbolAddress((void**)&kvh, g_kvh); cudaGetSymbolAddress((void**)&kvl, g_kvl);
    cudaGetSymbolAddress((void**)&ath, g_ath); cudaGetSymbolAddress((void**)&atl, g_atl);

    cudaFuncSetAttribute((const void*)gemm_bf3<0>,
                         cudaFuncAttributeMaxDynamicSharedMemorySize, SMEM_NK);
    cudaFuncSetAttribute((const void*)gemm_bf3<1>,
                         cudaFuncAttributeMaxDynamicSharedMemorySize, SMEM_NK);
    cudaFuncSetAttribute((const void*)flash_attn,
                         cudaFuncAttributeMaxDynamicSharedMemorySize, FSMEM);

    // 0) splits
    splitk<<<(BB*SS*HIDDEN/4 + 255)/256, 256>>>(x, xh, xl, BB*SS*HIDDEN/4);
    splitw_qkv<<<(NQKV*HIDDEN/4 + 255)/256, 256>>>(qw, kw, vw, wh, wl);
    splitk<<<(HIDDEN*HIDDEN/4 + 255)/256, 256>>>(ow, owh, owl, HIDDEN*HIDDEN/4);

    // 1) fused QKV projection: [4096,2304] = X @ [Qw*s;Kw;Vw]^T
    gemm_bf3<0><<<dim3(NQKV/BN, (BB*SS)/BM), 256, SMEM_NK>>>(
        xh, xl, wh, wl, qh, ql, kvh, kvl, nullptr);

    // 2) fused attention -> attn pair
    flash_attn<<<dim3(SS/TQ, BB*HEADS), 256, FSMEM>>>(
        qh, ql, kvh, kvl, ath, atl);

    // 3) out = attn @ Ow^T -> fp32
    gemm_bf3<1><<<dim3(HIDDEN/BN, (BB*SS)/BM), 256, SMEM_NK>>>(
        ath, atl, owh, owl, nullptr, nullptr, nullptr, nullptr, out);
}

// round 6
// speedup vs baseline: 3.6544x; 1.0221x over previous
#include <cuda_runtime.h>
#include <cuda_bf16.h>
#include <cstdint>

// ---------------------------------------------------------------------------
// ProductionFastMQA round 6:
//   * flash: exp/pack interleaved into PV MMA loop (MUFU/tensor overlap),
//     exp2-domain softmax (log2e folded into Qw), earlier K prefetch
//   * cheaper bf16x2 pack everywhere
//   * GEMMs unchanged from round 5
// ---------------------------------------------------------------------------

#define HIDDEN   2048
#define HEADS    16
#define HEAD_DIM 128
#define BB       2
#define SS       2048
#define SCALE    0.08838834764831845f     // 1/sqrt(128)
#define LOG2E    1.4426950408889634f
#define QSCALE   (SCALE * LOG2E)          // folded into Qw: scores in log2 domain
#define NQKV     2304
#define KVLD     256

// gemm tiles
#define BM   128
#define BN   128
#define BKb  32
#define ASTR (BKb + 8)
#define ASZ  (BM * ASTR)
#define SMEM_NK ((8 * ASZ) * 2)

// flash tiles
#define TQ 128
#define TK 128
#define DD 128
#define FSTR 136
#define FTB  (TQ * FSTR * 2)
#define FSMEM (6 * FTB)

// ----------------------------- scratch -------------------------------------
__device__ __nv_bfloat16 g_xh[BB*SS*HIDDEN],  g_xl[BB*SS*HIDDEN];
__device__ __nv_bfloat16 g_wh[NQKV*HIDDEN],   g_wl[NQKV*HIDDEN];
__device__ __nv_bfloat16 g_owh[HIDDEN*HIDDEN], g_owl[HIDDEN*HIDDEN];
__device__ __nv_bfloat16 g_qh[BB*SS*HIDDEN],  g_ql[BB*SS*HIDDEN];
__device__ __nv_bfloat16 g_kvh[BB*SS*KVLD],   g_kvl[BB*SS*KVLD];
__device__ __nv_bfloat16 g_ath[BB*SS*HIDDEN], g_atl[BB*SS*HIDDEN];

// ----------------------------- PTX helpers ---------------------------------
__device__ __forceinline__ uint32_t smem_u32(const void* p) {
    uint32_t a;
    asm("{ .reg .u64 t; cvta.to.shared.u64 t, %1; cvt.u32.u64 %0, t; }"
        : "=r"(a) : "l"(p));
    return a;
}
__device__ __forceinline__ void ldm4(uint32_t* r, uint32_t a) {
    asm volatile("ldmatrix.sync.aligned.m8n8.x4.shared.b16 {%0,%1,%2,%3},[%4];"
                 : "=r"(r[0]), "=r"(r[1]), "=r"(r[2]), "=r"(r[3]) : "r"(a));
}
__device__ __forceinline__ void ldm4t(uint32_t* r, uint32_t a) {
    asm volatile("ldmatrix.sync.aligned.m8n8.x4.trans.shared.b16 {%0,%1,%2,%3},[%4];"
                 : "=r"(r[0]), "=r"(r[1]), "=r"(r[2]), "=r"(r[3]) : "r"(a));
}
__device__ __forceinline__ void cpa16(uint32_t d, const void* s) {
    asm volatile("cp.async.cg.shared.global [%0],[%1],16;" :: "r"(d), "l"(s));
}
__device__ __forceinline__ void mma16(float* c, const uint32_t* a, const uint32_t* b) {
    asm volatile(
        "mma.sync.aligned.m16n8k16.row.col.f32.bf16.bf16.f32 "
        "{%0,%1,%2,%3},{%4,%5,%6,%7},{%8,%9},{%0,%1,%2,%3};"
        : "+f"(c[0]), "+f"(c[1]), "+f"(c[2]), "+f"(c[3])
        : "r"(a[0]), "r"(a[1]), "r"(a[2]), "r"(a[3]), "r"(b[0]), "r"(b[1]));
}
// pack (a,b) -> bf16x2 hi + bf16x2 residual lo.  .x=a (low 16), .y=b (high 16)
__device__ __forceinline__ void packpair(float a, float b, uint32_t& hi, uint32_t& lo) {
    uint32_t h;
    asm("cvt.rn.bf16x2.f32 %0, %1, %2;" : "=r"(h) : "f"(b), "f"(a));
    float fa = __uint_as_float(h << 16);
    float fb = __uint_as_float(h & 0xFFFF0000u);
    asm("cvt.rn.bf16x2.f32 %0, %1, %2;" : "=r"(lo) : "f"(b - fb), "f"(a - fa));
    hi = h;
}

// ---------------------------------------------------------------------------
// bf16x3 GEMM (round 5, unchanged).  A [M,2048] pair, B [N,2048] pair, C=A*B^T
// MODE 0: QKV routed pair outputs; MODE 1: fp32 output ldc=2048.
// ---------------------------------------------------------------------------
template <int MODE>
__global__ __launch_bounds__(256, 2) void gemm_bf3(
    const __nv_bfloat16* __restrict__ Ah, const __nv_bfloat16* __restrict__ Al,
    const __nv_bfloat16* __restrict__ Bh, const __nv_bfloat16* __restrict__ Bl,
    __nv_bfloat16* __restrict__ Qhi, __nv_bfloat16* __restrict__ Qlo,
    __nv_bfloat16* __restrict__ KVhi, __nv_bfloat16* __restrict__ KVlo,
    float* __restrict__ Cf)
{
    extern __shared__ __nv_bfloat16 sm[];
    const uint32_t as_base = smem_u32(sm);
    const uint32_t bs_base = as_base + 4 * ASZ * 2;

    const int tid = threadIdx.x, lane = tid & 31, warp = tid >> 5;
    const int wm0 = (warp >> 2) * 64;
    const int wn0 = (warp & 3) * 32;
    const int m0 = blockIdx.y * BM, n0 = blockIdx.x * BN;

    float acc[4][4][4] = {};
    const int ar = tid >> 2;
    const int ac = (tid & 3) * 8;

    auto ld_stage = [&](int kt, int st) {
#pragma unroll
        for (int i = 0; i < 2; i++) {
            int r = ar + i * 64;
            long long go = (long long)(m0 + r) * HIDDEN + kt + ac;
            uint32_t so = (uint32_t)(r * ASTR + ac) * 2;
            cpa16(as_base + (st*2+0)*ASZ*2 + so, Ah + go);
            cpa16(as_base + (st*2+1)*ASZ*2 + so, Al + go);
            long long gb = (long long)(n0 + r) * HIDDEN + kt + ac;
            cpa16(bs_base + (st*2+0)*ASZ*2 + so, Bh + gb);
            cpa16(bs_base + (st*2+1)*ASZ*2 + so, Bl + gb);
        }
    };

    ld_stage(0, 0);
    asm volatile("cp.async.commit_group;");

    const int T = HIDDEN / BKb;
    for (int t = 0; t < T; t++) {
        if (t + 1 < T) {
            ld_stage((t + 1) * BKb, (t + 1) & 1);
            asm volatile("cp.async.commit_group;");
            asm volatile("cp.async.wait_group 1;");
        } else {
            asm volatile("cp.async.wait_group 0;");
        }
        __syncthreads();
        const int st = t & 1;
        const uint32_t aH0 = as_base + (st*2+0)*ASZ*2;
        const uint32_t aL0 = as_base + (st*2+1)*ASZ*2;
        const uint32_t bH0 = bs_base + (st*2+0)*ASZ*2;
        const uint32_t bL0 = bs_base + (st*2+1)*ASZ*2;

#pragma unroll
        for (int kk = 0; kk < BKb; kk += 16) {
            uint32_t ah[4][4], al[4][4];
            const int arow = wm0 + (lane & 15);
            const int acol = kk + ((lane >> 4) << 3);
#pragma unroll
            for (int mi = 0; mi < 4; mi++) {
                uint32_t off = (uint32_t)((arow + mi*16) * ASTR + acol) * 2;
                ldm4(ah[mi], aH0 + off);
                ldm4(al[mi], aL0 + off);
            }
            uint32_t bh[4][2], bl[4][2];
            const int br = wn0 + ((lane >> 4) << 3) + (lane & 7);
            const int bc = kk + (((lane >> 3) & 1) << 3);
#pragma unroll
            for (int j = 0; j < 2; j++) {
                uint32_t off = (uint32_t)((br + j*16) * ASTR + bc) * 2;
                uint32_t r4[4];
                ldm4(r4, bH0 + off);
                bh[2*j][0]=r4[0]; bh[2*j][1]=r4[1]; bh[2*j+1][0]=r4[2]; bh[2*j+1][1]=r4[3];
                ldm4(r4, bL0 + off);
                bl[2*j][0]=r4[0]; bl[2*j][1]=r4[1]; bl[2*j+1][0]=r4[2]; bl[2*j+1][1]=r4[3];
            }
#pragma unroll
            for (int mi = 0; mi < 4; mi++)
#pragma unroll
                for (int ni = 0; ni < 4; ni++) {
                    mma16(acc[mi][ni], ah[mi], bh[ni]);
                    mma16(acc[mi][ni], ah[mi], bl[ni]);
                    mma16(acc[mi][ni], al[mi], bh[ni]);
                }
        }
        __syncthreads();
    }

    const int lr = lane >> 2, lc = lane & 3;
    if (MODE == 0) {
        const bool isQ = (n0 < HIDDEN);
        __nv_bfloat16* Oh = isQ ? Qhi : KVhi;
        __nv_bfloat16* Ol = isQ ? Qlo : KVlo;
        const int ldc = isQ ? HIDDEN : KVLD;
        const int cb  = isQ ? n0 : (n0 - HIDDEN);
#pragma unroll
        for (int mi = 0; mi < 4; mi++)
#pragma unroll
            for (int ni = 0; ni < 4; ni++) {
                const int row = m0 + wm0 + mi*16 + lr;
                const int col = cb + wn0 + ni*8 + 2*lc;
#pragma unroll
                for (int hf = 0; hf < 2; hf++) {
                    uint32_t hh, ll;
                    packpair(acc[mi][ni][2*hf], acc[mi][ni][2*hf + 1], hh, ll);
                    long long o = (long long)(row + 8*hf) * ldc + col;
                    *(uint32_t*)(Oh + o) = hh;
                    *(uint32_t*)(Ol + o) = ll;
                }
            }
    } else {
#pragma unroll
        for (int mi = 0; mi < 4; mi++)
#pragma unroll
            for (int ni = 0; ni < 4; ni++) {
                const int row = m0 + wm0 + mi*16 + lr;
                const int col = n0 + wn0 + ni*8 + 2*lc;
                long long o = (long long)row * HIDDEN + col;
                *(float2*)(Cf + o) = make_float2(acc[mi][ni][0], acc[mi][ni][1]);
                *(float2*)(Cf + o + 8LL * HIDDEN) =
                    make_float2(acc[mi][ni][2], acc[mi][ni][3]);
            }
    }
}

// ------------------------- split kernels ------------------------------------
__global__ __launch_bounds__(256) void splitk(
    const float* __restrict__ in, __nv_bfloat16* __restrict__ hi,
    __nv_bfloat16* __restrict__ lo, int n4)
{
    int i = blockIdx.x * 256 + threadIdx.x;
    if (i >= n4) return;
    float4 v = ((const float4*)in)[i];
    uint32_t h0, l0, h1, l1;
    packpair(v.x, v.y, h0, l0);
    packpair(v.z, v.w, h1, l1);
    ((uint32_t*)hi)[2*i]     = h0;
    ((uint32_t*)hi)[2*i + 1] = h1;
    ((uint32_t*)lo)[2*i]     = l0;
    ((uint32_t*)lo)[2*i + 1] = l1;
}

// pack [Qw*QSCALE ; Kw ; Vw] -> combined [2304,2048] hi/lo
__global__ __launch_bounds__(256) void splitw_qkv(
    const float* __restrict__ qw, const float* __restrict__ kw,
    const float* __restrict__ vw, __nv_bfloat16* __restrict__ wh,
    __nv_bfloat16* __restrict__ wl)
{
    int i = blockIdx.x * 256 + threadIdx.x;
    if (i >= NQKV * HIDDEN / 4) return;
    long long e = (long long)i * 4;
    int r = (int)(e >> 11);
    int c = (int)(e & 2047);
    const float* src;
    float sc = 1.0f;
    if (r < 2048)      { src = qw + ((long long)r << 11) + c; sc = QSCALE; }
    else if (r < 2176) { src = kw + ((long long)(r - 2048) << 11) + c; }
    else               { src = vw + ((long long)(r - 2176) << 11) + c; }
    float4 v = *(const float4*)src;
    uint32_t h0, l0, h1, l1;
    packpair(v.x * sc, v.y * sc, h0, l0);
    packpair(v.z * sc, v.w * sc, h1, l1);
    ((uint32_t*)wh)[2*i]     = h0;
    ((uint32_t*)wh)[2*i + 1] = h1;
    ((uint32_t*)wl)[2*i]     = l0;
    ((uint32_t*)wl)[2*i + 1] = l1;
}

// ---------------------------------------------------------------------------
// Flash attention, exp2-domain softmax (Q pre-scaled by SCALE*log2e).
// exp/pack interleaved into the PV MMA chunk loop for MUFU/tensor overlap.
// ---------------------------------------------------------------------------
__global__ __launch_bounds__(256, 1) void flash_attn(
    const __nv_bfloat16* __restrict__ Qh_, const __nv_bfloat16* __restrict__ Ql_,
    const __nv_bfloat16* __restrict__ KVh_, const __nv_bfloat16* __restrict__ KVl_,
    __nv_bfloat16* __restrict__ Oh_, __nv_bfloat16* __restrict__ Ol_)
{
    extern __shared__ __nv_bfloat16 fsm[];
    const int b = blockIdx.y >> 4, h = blockIdx.y & 15;
    const int q0 = blockIdx.x * TQ;
    const int tid = threadIdx.x, lane = tid & 31, warp = tid >> 5;
    const int lr = lane >> 2, lc = lane & 3;

    const uint32_t s0 = smem_u32(fsm);
    const uint32_t sVh = s0 + 4*FTB, sVl = s0 + 5*FTB;

    // ---- stage Q via V buffers, hoist fragments to registers ----
#pragma unroll
    for (int i = 0; i < 8; i++) {
        int id = tid + i * 256;
        int r = id >> 4, c = (id & 15) * 8;
        uint32_t so = (uint32_t)(r * FSTR + c) * 2;
        long long gq = (long long)(b * SS + q0 + r) * HIDDEN + h * DD + c;
        cpa16(sVh + so, Qh_ + gq);
        cpa16(sVl + so, Ql_ + gq);
    }
    asm volatile("cp.async.commit_group;");
    asm volatile("cp.async.wait_group 0;");
    __syncthreads();

    uint32_t qhr[8][4], qlr[8][4];
#pragma unroll
    for (int kk = 0; kk < 8; kk++) {
        uint32_t aoff = (uint32_t)((warp*16 + (lane & 15)) * FSTR
                                   + kk*16 + ((lane >> 4) << 3)) * 2;
        ldm4(qhr[kk], sVh + aoff);
        ldm4(qlr[kk], sVl + aoff);
    }
    __syncthreads();

    // ---- K(0) prefetch ----
#pragma unroll
    for (int i = 0; i < 8; i++) {
        int id = tid + i * 256;
        int r = id >> 4, c = (id & 15) * 8;
        uint32_t so = (uint32_t)(r * FSTR + c) * 2;
        long long gk = (long long)(b * SS + r) * KVLD + c;
        cpa16(s0 + so, KVh_ + gk);
        cpa16(s0 + FTB + so, KVl_ + gk);
    }
    asm volatile("cp.async.commit_group;");      // pending: {K0}

    float oacc[16][4] = {};
    float mrow[2] = {-1e30f, -1e30f};
    float lrow[2] = {0.f, 0.f};

    for (int t = 0; t < SS / TK; t++) {
        const uint32_t sKh = s0 + ((t & 1) ? 2 : 0) * FTB;
        const uint32_t sKl = sKh + FTB;

        // V(t) prefetch
#pragma unroll
        for (int i = 0; i < 8; i++) {
            int id = tid + i * 256;
            int r = id >> 4, c = (id & 15) * 8;
            uint32_t so = (uint32_t)(r * FSTR + c) * 2;
            long long gv = (long long)(b * SS + t * TK + r) * KVLD + 128 + c;
            cpa16(sVh + so, KVh_ + gv);
            cpa16(sVl + so, KVl_ + gv);
        }
        asm volatile("cp.async.commit_group;");  // pending: {K(t), V(t)}
        asm volatile("cp.async.wait_group 1;");  // K(t) landed
        __syncthreads();

        // K(t+1) prefetch immediately (full iteration of flight time)
        if (t + 1 < SS / TK) {
            const uint32_t dKh = s0 + (((t + 1) & 1) ? 2 : 0) * FTB;
#pragma unroll
            for (int i = 0; i < 8; i++) {
                int id = tid + i * 256;
                int r = id >> 4, c = (id & 15) * 8;
                uint32_t so = (uint32_t)(r * FSTR + c) * 2;
                long long gk = (long long)(b * SS + (t + 1) * TK + r) * KVLD + c;
                cpa16(dKh + so, KVh_ + gk);
                cpa16(dKh + FTB + so, KVl_ + gk);
            }
            asm volatile("cp.async.commit_group;"); // pending: {V(t), K(t+1)}
        }

        // ---- S = Q K^T (log2 domain) ----
        float sacc[16][4] = {};
#pragma unroll
        for (int kk = 0; kk < 8; kk++) {
#pragma unroll
            for (int j = 0; j < 8; j++) {
                uint32_t boff = (uint32_t)((j*16 + ((lane >> 4) << 3) + (lane & 7)) * FSTR
                                           + kk*16 + (((lane >> 3) & 1) << 3)) * 2;
                uint32_t kh4[4], kl4[4];
                ldm4(kh4, sKh + boff);
                ldm4(kl4, sKl + boff);
                mma16(sacc[2*j],   qhr[kk], kh4);     mma16(sacc[2*j],   qlr[kk], kh4);
                mma16(sacc[2*j],   qhr[kk], kl4);
                mma16(sacc[2*j+1], qhr[kk], kh4 + 2); mma16(sacc[2*j+1], qlr[kk], kh4 + 2);
                mma16(sacc[2*j+1], qhr[kk], kl4 + 2);
            }
        }

        // ---- row max + rescale ----
        float tm0 = -1e30f, tm1 = -1e30f;
#pragma unroll
        for (int ni = 0; ni < 16; ni++) {
            tm0 = fmaxf(tm0, fmaxf(sacc[ni][0], sacc[ni][1]));
            tm1 = fmaxf(tm1, fmaxf(sacc[ni][2], sacc[ni][3]));
        }
        tm0 = fmaxf(tm0, __shfl_xor_sync(0xffffffffu, tm0, 1));
        tm0 = fmaxf(tm0, __shfl_xor_sync(0xffffffffu, tm0, 2));
        tm1 = fmaxf(tm1, __shfl_xor_sync(0xffffffffu, tm1, 1));
        tm1 = fmaxf(tm1, __shfl_xor_sync(0xffffffffu, tm1, 2));
        const float mn0 = fmaxf(mrow[0], tm0), mn1 = fmaxf(mrow[1], tm1);
        const float f0 = exp2f(mrow[0] - mn0), f1 = exp2f(mrow[1] - mn1);
        mrow[0] = mn0; mrow[1] = mn1;
#pragma unroll
        for (int nd = 0; nd < 16; nd++) {
            oacc[nd][0] *= f0; oacc[nd][1] *= f0;
            oacc[nd][2] *= f1; oacc[nd][3] *= f1;
        }

        if (t + 1 < SS / TK) {
            asm volatile("cp.async.wait_group 1;"); // V(t) landed, K(t+1) flying
        } else {
            asm volatile("cp.async.wait_group 0;");
        }
        __syncthreads();

        // ---- PV with exp/pack interleaved per chunk ----
        float rs0 = 0.f, rs1 = 0.f;
#pragma unroll
        for (int c = 0; c < 8; c++) {
            float e00 = exp2f(sacc[2*c][0]   - mn0);
            float e01 = exp2f(sacc[2*c][1]   - mn0);
            float e02 = exp2f(sacc[2*c][2]   - mn1);
            float e03 = exp2f(sacc[2*c][3]   - mn1);
            float e10 = exp2f(sacc[2*c+1][0] - mn0);
            float e11 = exp2f(sacc[2*c+1][1] - mn0);
            float e12 = exp2f(sacc[2*c+1][2] - mn1);
            float e13 = exp2f(sacc[2*c+1][3] - mn1);
            rs0 += (e00 + e01) + (e10 + e11);
            rs1 += (e02 + e03) + (e12 + e13);
            uint32_t ph4[4], pl4[4];
            packpair(e00, e01, ph4[0], pl4[0]);
            packpair(e02, e03, ph4[1], pl4[1]);
            packpair(e10, e11, ph4[2], pl4[2]);
            packpair(e12, e13, ph4[3], pl4[3]);
#pragma unroll
            for (int j = 0; j < 8; j++) {
                uint32_t boff = (uint32_t)((c*16 + (((lane >> 3) & 1) << 3) + (lane & 7)) * FSTR
                                           + j*16 + ((lane >> 4) << 3)) * 2;
                uint32_t vh4[4], vl4[4];
                ldm4t(vh4, sVh + boff);
                ldm4t(vl4, sVl + boff);
                mma16(oacc[2*j],   ph4, vh4);     mma16(oacc[2*j],   pl4, vh4);
                mma16(oacc[2*j],   ph4, vl4);
                mma16(oacc[2*j+1], ph4, vh4 + 2); mma16(oacc[2*j+1], pl4, vh4 + 2);
                mma16(oacc[2*j+1], ph4, vl4 + 2);
            }
        }
        rs0 += __shfl_xor_sync(0xffffffffu, rs0, 1);
        rs0 += __shfl_xor_sync(0xffffffffu, rs0, 2);
        rs1 += __shfl_xor_sync(0xffffffffu, rs1, 1);
        rs1 += __shfl_xor_sync(0xffffffffu, rs1, 2);
        lrow[0] = lrow[0] * f0 + rs0;
        lrow[1] = lrow[1] * f1 + rs1;

        __syncthreads();   // V consumed by all warps before next overwrite
    }

    // ---- epilogue ----
    const float i0 = 1.f / lrow[0], i1 = 1.f / lrow[1];
    const long long orow0 = (long long)(b * SS + q0 + warp*16 + lr) * HIDDEN + h * DD;
    const long long orow1 = orow0 + 8LL * HIDDEN;
#pragma unroll
    for (int nd = 0; nd < 16; nd++) {
        const int col = nd * 8 + 2 * lc;
        uint32_t hh, ll;
        packpair(oacc[nd][0] * i0, oacc[nd][1] * i0, hh, ll);
        *(uint32_t*)(Oh_ + orow0 + col) = hh;
        *(uint32_t*)(Ol_ + orow0 + col) = ll;
        packpair(oacc[nd][2] * i1, oacc[nd][3] * i1, hh, ll);
        *(uint32_t*)(Oh_ + orow1 + col) = hh;
        *(uint32_t*)(Ol_ + orow1 + col) = ll;
    }
}

// ---------------------------------------------------------------------------

extern "C" void kernel_launch(void* const* d_in, const int* in_sizes, int n_in,
                              void* d_out, int out_size) {
    const float* x  = (const float*)d_in[0];
    const float* qw = (const float*)d_in[1];
    const float* kw = (const float*)d_in[2];
    const float* vw = (const float*)d_in[3];
    const float* ow = (const float*)d_in[4];
    float* out = (float*)d_out;

    __nv_bfloat16 *xh,*xl,*wh,*wl,*owh,*owl,*qh,*ql,*kvh,*kvl,*ath,*atl;
    cudaGetSymbolAddress((void**)&xh,  g_xh);  cudaGetSymbolAddress((void**)&xl,  g_xl);
    cudaGetSymbolAddress((void**)&wh,  g_wh);  cudaGetSymbolAddress((void**)&wl,  g_wl);
    cudaGetSymbolAddress((void**)&owh, g_owh); cudaGetSymbolAddress((void**)&owl, g_owl);
    cudaGetSymbolAddress((void**)&qh,  g_qh);  cudaGetSymbolAddress((void**)&ql,  g_ql);
    cudaGetSymbolAddress((void**)&kvh, g_kvh); cudaGetSymbolAddress((void**)&kvl, g_kvl);
    cudaGetSymbolAddress((void**)&ath, g_ath); cudaGetSymbolAddress((void**)&atl, g_atl);

    cudaFuncSetAttribute((const void*)gemm_bf3<0>,
                         cudaFuncAttributeMaxDynamicSharedMemorySize, SMEM_NK);
    cudaFuncSetAttribute((const void*)gemm_bf3<1>,
                         cudaFuncAttributeMaxDynamicSharedMemorySize, SMEM_NK);
    cudaFuncSetAttribute((const void*)flash_attn,
                         cudaFuncAttributeMaxDynamicSharedMemorySize, FSMEM);

    // 0) splits
    splitk<<<(BB*SS*HIDDEN/4 + 255)/256, 256>>>(x, xh, xl, BB*SS*HIDDEN/4);
    splitw_qkv<<<(NQKV*HIDDEN/4 + 255)/256, 256>>>(qw, kw, vw, wh, wl);
    splitk<<<(HIDDEN*HIDDEN/4 + 255)/256, 256>>>(ow, owh, owl, HIDDEN*HIDDEN/4);

    // 1) fused QKV projection
    gemm_bf3<0><<<dim3(NQKV/BN, (BB*SS)/BM), 256, SMEM_NK>>>(
        xh, xl, wh, wl, qh, ql, kvh, kvl, nullptr);

    // 2) fused attention
    flash_attn<<<dim3(SS/TQ, BB*HEADS), 256, FSMEM>>>(
        qh, ql, kvh, kvl, ath, atl);

    // 3) out = attn @ Ow^T
    gemm_bf3<1><<<dim3(HIDDEN/BN, (BB*SS)/BM), 256, SMEM_NK>>>(
        ath, atl, owh, owl, nullptr, nullptr, nullptr, nullptr, out);
}

// round 7
// speedup vs baseline: 5.2217x; 1.4289x over previous
#include <cuda_runtime.h>
#include <cuda_fp16.h>
#include <cstdint>

// ---------------------------------------------------------------------------
// ProductionFastMQA round 7: fp16x2 scheme everywhere.
//   A-operand split into fp16 hi/lo (error ~2^-22), B-operand single rounded
//   fp16 (error ~1.4e-4/stage). 2 MMAs per K=16 instead of 3 -> 1/3 fewer
//   tensor ops in QKV, QK^T, PV, O-proj. B smem/gmem traffic halved.
// ---------------------------------------------------------------------------

#define HIDDEN   2048
#define HEADS    16
#define HEAD_DIM 128
#define BB       2
#define SS       2048
#define SCALE    0.08838834764831845f
#define LOG2E    1.4426950408889634f
#define QSCALE   (SCALE * LOG2E)          // folded into Qw (log2-domain scores)
#define NQKV     2304
#define KVLD     256

// gemm tiles
#define BM   128
#define BN   128
#define BKb  32
#define ASTR (BKb + 8)          // 40 halves
#define ASZ  (BM * ASTR)        // 5120
#define SMEM_NK ((6 * ASZ) * 2) // 61440 B: A 2stages x hi/lo + B 2stages

// flash tiles
#define TQ 128
#define TK 128
#define DD 128
#define FSTR 136
#define FTB  (TQ * FSTR * 2)    // 34816 B
#define FSMEM (3 * FTB)         // K0, K1, V = 104448 B

// ----------------------------- scratch -------------------------------------
__device__ __half g_xh[BB*SS*HIDDEN],  g_xl[BB*SS*HIDDEN];
__device__ __half g_w[NQKV*HIDDEN];                    // QKV weights, fp16
__device__ __half g_ow[HIDDEN*HIDDEN];                 // O weights, fp16
__device__ __half g_qh[BB*SS*HIDDEN],  g_ql[BB*SS*HIDDEN];
__device__ __half g_kv[BB*SS*KVLD];                    // K|V combined, fp16
__device__ __half g_ath[BB*SS*HIDDEN], g_atl[BB*SS*HIDDEN];

// ----------------------------- PTX helpers ---------------------------------
__device__ __forceinline__ uint32_t smem_u32(const void* p) {
    uint32_t a;
    asm("{ .reg .u64 t; cvta.to.shared.u64 t, %1; cvt.u32.u64 %0, t; }"
        : "=r"(a) : "l"(p));
    return a;
}
__device__ __forceinline__ void ldm4(uint32_t* r, uint32_t a) {
    asm volatile("ldmatrix.sync.aligned.m8n8.x4.shared.b16 {%0,%1,%2,%3},[%4];"
                 : "=r"(r[0]), "=r"(r[1]), "=r"(r[2]), "=r"(r[3]) : "r"(a));
}
__device__ __forceinline__ void ldm4t(uint32_t* r, uint32_t a) {
    asm volatile("ldmatrix.sync.aligned.m8n8.x4.trans.shared.b16 {%0,%1,%2,%3},[%4];"
                 : "=r"(r[0]), "=r"(r[1]), "=r"(r[2]), "=r"(r[3]) : "r"(a));
}
__device__ __forceinline__ void cpa16(uint32_t d, const void* s) {
    asm volatile("cp.async.cg.shared.global [%0],[%1],16;" :: "r"(d), "l"(s));
}
__device__ __forceinline__ void mma16(float* c, const uint32_t* a, const uint32_t* b) {
    asm volatile(
        "mma.sync.aligned.m16n8k16.row.col.f32.f16.f16.f32 "
        "{%0,%1,%2,%3},{%4,%5,%6,%7},{%8,%9},{%0,%1,%2,%3};"
        : "+f"(c[0]), "+f"(c[1]), "+f"(c[2]), "+f"(c[3])
        : "r"(a[0]), "r"(a[1]), "r"(a[2]), "r"(a[3]), "r"(b[0]), "r"(b[1]));
}
// (a,b) -> fp16x2 hi + fp16x2 residual lo (low half = a)
__device__ __forceinline__ void packpair(float a, float b, uint32_t& hi, uint32_t& lo) {
    __half2 H = __floats2half2_rn(a, b);
    float2 F = __half22float2(H);
    __half2 L = __floats2half2_rn(a - F.x, b - F.y);
    hi = *reinterpret_cast<const uint32_t*>(&H);
    lo = *reinterpret_cast<const uint32_t*>(&L);
}

// ---------------------------------------------------------------------------
// fp16x2 GEMM: C = (Ah+Al)[M,2048] @ (B[N,2048])^T, 2 MMAs per k16.
// MODE 0: QKV — Q cols -> fp16 pair, KV cols -> single fp16.
// MODE 1: fp32 output, ldc=2048.
// ---------------------------------------------------------------------------
template <int MODE>
__global__ __launch_bounds__(256, 2) void gemm_f16(
    const __half* __restrict__ Ah, const __half* __restrict__ Al,
    const __half* __restrict__ Bh,
    __half* __restrict__ Qhi, __half* __restrict__ Qlo,
    __half* __restrict__ KVo, float* __restrict__ Cf)
{
    extern __shared__ __half sm[];
    const uint32_t as_base = smem_u32(sm);             // 4 planes: (st,h/l)
    const uint32_t bs_base = as_base + 4 * ASZ * 2;    // 2 planes: st

    const int tid = threadIdx.x, lane = tid & 31, warp = tid >> 5;
    const int wm0 = (warp >> 2) * 64;
    const int wn0 = (warp & 3) * 32;
    const int m0 = blockIdx.y * BM, n0 = blockIdx.x * BN;

    float acc[4][4][4] = {};
    const int ar = tid >> 2;
    const int ac = (tid & 3) * 8;

    auto ld_stage = [&](int kt, int st) {
#pragma unroll
        for (int i = 0; i < 2; i++) {
            int r = ar + i * 64;
            long long go = (long long)(m0 + r) * HIDDEN + kt + ac;
            uint32_t so = (uint32_t)(r * ASTR + ac) * 2;
            cpa16(as_base + (st*2+0)*ASZ*2 + so, Ah + go);
            cpa16(as_base + (st*2+1)*ASZ*2 + so, Al + go);
            long long gb = (long long)(n0 + r) * HIDDEN + kt + ac;
            cpa16(bs_base + st*ASZ*2 + so, Bh + gb);
        }
    };

    ld_stage(0, 0);
    asm volatile("cp.async.commit_group;");

    const int T = HIDDEN / BKb;
    for (int t = 0; t < T; t++) {
        if (t + 1 < T) {
            ld_stage((t + 1) * BKb, (t + 1) & 1);
            asm volatile("cp.async.commit_group;");
            asm volatile("cp.async.wait_group 1;");
        } else {
            asm volatile("cp.async.wait_group 0;");
        }
        __syncthreads();
        const int st = t & 1;
        const uint32_t aH0 = as_base + (st*2+0)*ASZ*2;
        const uint32_t aL0 = as_base + (st*2+1)*ASZ*2;
        const uint32_t bH0 = bs_base + st*ASZ*2;

#pragma unroll
        for (int kk = 0; kk < BKb; kk += 16) {
            uint32_t ah[4][4], al[4][4];
            const int arow = wm0 + (lane & 15);
            const int acol = kk + ((lane >> 4) << 3);
#pragma unroll
            for (int mi = 0; mi < 4; mi++) {
                uint32_t off = (uint32_t)((arow + mi*16) * ASTR + acol) * 2;
                ldm4(ah[mi], aH0 + off);
                ldm4(al[mi], aL0 + off);
            }
            uint32_t bh[4][2];
            const int br = wn0 + ((lane >> 4) << 3) + (lane & 7);
            const int bc = kk + (((lane >> 3) & 1) << 3);
#pragma unroll
            for (int j = 0; j < 2; j++) {
                uint32_t off = (uint32_t)((br + j*16) * ASTR + bc) * 2;
                uint32_t r4[4];
                ldm4(r4, bH0 + off);
                bh[2*j][0]=r4[0]; bh[2*j][1]=r4[1]; bh[2*j+1][0]=r4[2]; bh[2*j+1][1]=r4[3];
            }
#pragma unroll
            for (int mi = 0; mi < 4; mi++)
#pragma unroll
                for (int ni = 0; ni < 4; ni++) {
                    mma16(acc[mi][ni], ah[mi], bh[ni]);
                    mma16(acc[mi][ni], al[mi], bh[ni]);
                }
        }
        __syncthreads();
    }

    const int lr = lane >> 2, lc = lane & 3;
    if (MODE == 0) {
        const bool isQ = (n0 < HIDDEN);
        if (isQ) {
#pragma unroll
            for (int mi = 0; mi < 4; mi++)
#pragma unroll
                for (int ni = 0; ni < 4; ni++) {
                    const int row = m0 + wm0 + mi*16 + lr;
                    const int col = n0 + wn0 + ni*8 + 2*lc;
#pragma unroll
                    for (int hf = 0; hf < 2; hf++) {
                        uint32_t hh, ll;
                        packpair(acc[mi][ni][2*hf], acc[mi][ni][2*hf + 1], hh, ll);
                        long long o = (long long)(row + 8*hf) * HIDDEN + col;
                        *(uint32_t*)(Qhi + o) = hh;
                        *(uint32_t*)(Qlo + o) = ll;
                    }
                }
        } else {
            const int cb = n0 - HIDDEN;
#pragma unroll
            for (int mi = 0; mi < 4; mi++)
#pragma unroll
                for (int ni = 0; ni < 4; ni++) {
                    const int row = m0 + wm0 + mi*16 + lr;
                    const int col = cb + wn0 + ni*8 + 2*lc;
#pragma unroll
                    for (int hf = 0; hf < 2; hf++) {
                        __half2 hv = __floats2half2_rn(acc[mi][ni][2*hf],
                                                       acc[mi][ni][2*hf + 1]);
                        long long o = (long long)(row + 8*hf) * KVLD + col;
                        *(__half2*)(KVo + o) = hv;
                    }
                }
        }
    } else {
#pragma unroll
        for (int mi = 0; mi < 4; mi++)
#pragma unroll
            for (int ni = 0; ni < 4; ni++) {
                const int row = m0 + wm0 + mi*16 + lr;
                const int col = n0 + wn0 + ni*8 + 2*lc;
                long long o = (long long)row * HIDDEN + col;
                *(float2*)(Cf + o) = make_float2(acc[mi][ni][0], acc[mi][ni][1]);
                *(float2*)(Cf + o + 8LL * HIDDEN) =
                    make_float2(acc[mi][ni][2], acc[mi][ni][3]);
            }
    }
}

// ------------------------- split / round kernels ----------------------------
__global__ __launch_bounds__(256) void splitk(
    const float* __restrict__ in, __half* __restrict__ hi,
    __half* __restrict__ lo, int n4)
{
    int i = blockIdx.x * 256 + threadIdx.x;
    if (i >= n4) return;
    float4 v = ((const float4*)in)[i];
    uint32_t h0, l0, h1, l1;
    packpair(v.x, v.y, h0, l0);
    packpair(v.z, v.w, h1, l1);
    ((uint32_t*)hi)[2*i]     = h0;
    ((uint32_t*)hi)[2*i + 1] = h1;
    ((uint32_t*)lo)[2*i]     = l0;
    ((uint32_t*)lo)[2*i + 1] = l1;
}

// round fp32 -> fp16 (O weights)
__global__ __launch_bounds__(256) void roundk(
    const float* __restrict__ in, __half* __restrict__ out, int n4)
{
    int i = blockIdx.x * 256 + threadIdx.x;
    if (i >= n4) return;
    float4 v = ((const float4*)in)[i];
    ((__half2*)out)[2*i]     = __floats2half2_rn(v.x, v.y);
    ((__half2*)out)[2*i + 1] = __floats2half2_rn(v.z, v.w);
}

// pack [Qw*QSCALE ; Kw ; Vw] -> [2304,2048] fp16
__global__ __launch_bounds__(256) void splitw_qkv(
    const float* __restrict__ qw, const float* __restrict__ kw,
    const float* __restrict__ vw, __half* __restrict__ w)
{
    int i = blockIdx.x * 256 + threadIdx.x;
    if (i >= NQKV * HIDDEN / 4) return;
    long long e = (long long)i * 4;
    int r = (int)(e >> 11);
    int c = (int)(e & 2047);
    const float* src;
    float sc = 1.0f;
    if (r < 2048)      { src = qw + ((long long)r << 11) + c; sc = QSCALE; }
    else if (r < 2176) { src = kw + ((long long)(r - 2048) << 11) + c; }
    else               { src = vw + ((long long)(r - 2176) << 11) + c; }
    float4 v = *(const float4*)src;
    ((__half2*)w)[2*i]     = __floats2half2_rn(v.x * sc, v.y * sc);
    ((__half2*)w)[2*i + 1] = __floats2half2_rn(v.z * sc, v.w * sc);
}

// ---------------------------------------------------------------------------
// Flash attention (fp16x2): Q pair in registers, K/V single fp16 planes.
// Double-buffered K, single V buffer; exp2-domain softmax interleaved in PV.
// ---------------------------------------------------------------------------
__global__ __launch_bounds__(256, 1) void flash_attn(
    const __half* __restrict__ Qh_, const __half* __restrict__ Ql_,
    const __half* __restrict__ KV_,
    __half* __restrict__ Oh_, __half* __restrict__ Ol_)
{
    extern __shared__ __half fsm[];
    const int b = blockIdx.y >> 4, h = blockIdx.y & 15;
    const int q0 = blockIdx.x * TQ;
    const int tid = threadIdx.x, lane = tid & 31, warp = tid >> 5;
    const int lr = lane >> 2, lc = lane & 3;

    const uint32_t s0 = smem_u32(fsm);
    const uint32_t sK0 = s0, sK1 = s0 + FTB, sV = s0 + 2*FTB;

    // ---- stage Qh->V plane, Ql->K1 plane; hoist to registers ----
#pragma unroll
    for (int i = 0; i < 8; i++) {
        int id = tid + i * 256;
        int r = id >> 4, c = (id & 15) * 8;
        uint32_t so = (uint32_t)(r * FSTR + c) * 2;
        long long gq = (long long)(b * SS + q0 + r) * HIDDEN + h * DD + c;
        cpa16(sV + so, Qh_ + gq);
        cpa16(sK1 + so, Ql_ + gq);
    }
    asm volatile("cp.async.commit_group;");
    asm volatile("cp.async.wait_group 0;");
    __syncthreads();

    uint32_t qhr[8][4], qlr[8][4];
#pragma unroll
    for (int kk = 0; kk < 8; kk++) {
        uint32_t aoff = (uint32_t)((warp*16 + (lane & 15)) * FSTR
                                   + kk*16 + ((lane >> 4) << 3)) * 2;
        ldm4(qhr[kk], sV + aoff);
        ldm4(qlr[kk], sK1 + aoff);
    }
    __syncthreads();

    // ---- K(0) prefetch ----
#pragma unroll
    for (int i = 0; i < 8; i++) {
        int id = tid + i * 256;
        int r = id >> 4, c = (id & 15) * 8;
        uint32_t so = (uint32_t)(r * FSTR + c) * 2;
        cpa16(sK0 + so, KV_ + (long long)(b * SS + r) * KVLD + c);
    }
    asm volatile("cp.async.commit_group;");      // pending: {K0}

    float oacc[16][4] = {};
    float mrow[2] = {-1e30f, -1e30f};
    float lrow[2] = {0.f, 0.f};

    for (int t = 0; t < SS / TK; t++) {
        const uint32_t sKh = (t & 1) ? sK1 : sK0;

        // V(t) prefetch
#pragma unroll
        for (int i = 0; i < 8; i++) {
            int id = tid + i * 256;
            int r = id >> 4, c = (id & 15) * 8;
            uint32_t so = (uint32_t)(r * FSTR + c) * 2;
            cpa16(sV + so, KV_ + (long long)(b * SS + t * TK + r) * KVLD + 128 + c);
        }
        asm volatile("cp.async.commit_group;");  // pending: {K(t), V(t)}
        asm volatile("cp.async.wait_group 1;");  // K(t) landed
        __syncthreads();

        // K(t+1) prefetch (full iteration of flight)
        if (t + 1 < SS / TK) {
            const uint32_t dK = ((t + 1) & 1) ? sK1 : sK0;
#pragma unroll
            for (int i = 0; i < 8; i++) {
                int id = tid + i * 256;
                int r = id >> 4, c = (id & 15) * 8;
                uint32_t so = (uint32_t)(r * FSTR + c) * 2;
                cpa16(dK + so, KV_ + (long long)(b * SS + (t + 1) * TK + r) * KVLD + c);
            }
            asm volatile("cp.async.commit_group;"); // pending: {V(t), K(t+1)}
        }

        // ---- S = Q K^T (log2 domain) ----
        float sacc[16][4] = {};
#pragma unroll
        for (int kk = 0; kk < 8; kk++) {
#pragma unroll
            for (int j = 0; j < 8; j++) {
                uint32_t boff = (uint32_t)((j*16 + ((lane >> 4) << 3) + (lane & 7)) * FSTR
                                           + kk*16 + (((lane >> 3) & 1) << 3)) * 2;
                uint32_t kh4[4];
                ldm4(kh4, sKh + boff);
                mma16(sacc[2*j],   qhr[kk], kh4);     mma16(sacc[2*j],   qlr[kk], kh4);
                mma16(sacc[2*j+1], qhr[kk], kh4 + 2); mma16(sacc[2*j+1], qlr[kk], kh4 + 2);
            }
        }

        // ---- row max + rescale ----
        float tm0 = -1e30f, tm1 = -1e30f;
#pragma unroll
        for (int ni = 0; ni < 16; ni++) {
            tm0 = fmaxf(tm0, fmaxf(sacc[ni][0], sacc[ni][1]));
            tm1 = fmaxf(tm1, fmaxf(sacc[ni][2], sacc[ni][3]));
        }
        tm0 = fmaxf(tm0, __shfl_xor_sync(0xffffffffu, tm0, 1));
        tm0 = fmaxf(tm0, __shfl_xor_sync(0xffffffffu, tm0, 2));
        tm1 = fmaxf(tm1, __shfl_xor_sync(0xffffffffu, tm1, 1));
        tm1 = fmaxf(tm1, __shfl_xor_sync(0xffffffffu, tm1, 2));
        const float mn0 = fmaxf(mrow[0], tm0), mn1 = fmaxf(mrow[1], tm1);
        const float f0 = exp2f(mrow[0] - mn0), f1 = exp2f(mrow[1] - mn1);
        mrow[0] = mn0; mrow[1] = mn1;
#pragma unroll
        for (int nd = 0; nd < 16; nd++) {
            oacc[nd][0] *= f0; oacc[nd][1] *= f0;
            oacc[nd][2] *= f1; oacc[nd][3] *= f1;
        }

        if (t + 1 < SS / TK) {
            asm volatile("cp.async.wait_group 1;"); // V(t) landed
        } else {
            asm volatile("cp.async.wait_group 0;");
        }
        __syncthreads();

        // ---- PV with exp/pack interleaved ----
        float rs0 = 0.f, rs1 = 0.f;
#pragma unroll
        for (int c = 0; c < 8; c++) {
            float e00 = exp2f(sacc[2*c][0]   - mn0);
            float e01 = exp2f(sacc[2*c][1]   - mn0);
            float e02 = exp2f(sacc[2*c][2]   - mn1);
            float e03 = exp2f(sacc[2*c][3]   - mn1);
            float e10 = exp2f(sacc[2*c+1][0] - mn0);
            float e11 = exp2f(sacc[2*c+1][1] - mn0);
            float e12 = exp2f(sacc[2*c+1][2] - mn1);
            float e13 = exp2f(sacc[2*c+1][3] - mn1);
            rs0 += (e00 + e01) + (e10 + e11);
            rs1 += (e02 + e03) + (e12 + e13);
            uint32_t ph4[4], pl4[4];
            packpair(e00, e01, ph4[0], pl4[0]);
            packpair(e02, e03, ph4[1], pl4[1]);
            packpair(e10, e11, ph4[2], pl4[2]);
            packpair(e12, e13, ph4[3], pl4[3]);
#pragma unroll
            for (int j = 0; j < 8; j++) {
                uint32_t boff = (uint32_t)((c*16 + (((lane >> 3) & 1) << 3) + (lane & 7)) * FSTR
                                           + j*16 + ((lane >> 4) << 3)) * 2;
                uint32_t vh4[4];
                ldm4t(vh4, sV + boff);
                mma16(oacc[2*j],   ph4, vh4);     mma16(oacc[2*j],   pl4, vh4);
                mma16(oacc[2*j+1], ph4, vh4 + 2); mma16(oacc[2*j+1], pl4, vh4 + 2);
            }
        }
        rs0 += __shfl_xor_sync(0xffffffffu, rs0, 1);
        rs0 += __shfl_xor_sync(0xffffffffu, rs0, 2);
        rs1 += __shfl_xor_sync(0xffffffffu, rs1, 1);
        rs1 += __shfl_xor_sync(0xffffffffu, rs1, 2);
        lrow[0] = lrow[0] * f0 + rs0;
        lrow[1] = lrow[1] * f1 + rs1;

        __syncthreads();
    }

    // ---- epilogue: O /= l, write fp16 pair ----
    const float i0 = 1.f / lrow[0], i1 = 1.f / lrow[1];
    const long long orow0 = (long long)(b * SS + q0 + warp*16 + lr) * HIDDEN + h * DD;
    const long long orow1 = orow0 + 8LL * HIDDEN;
#pragma unroll
    for (int nd = 0; nd < 16; nd++) {
        const int col = nd * 8 + 2 * lc;
        uint32_t hh, ll;
        packpair(oacc[nd][0] * i0, oacc[nd][1] * i0, hh, ll);
        *(uint32_t*)(Oh_ + orow0 + col) = hh;
        *(uint32_t*)(Ol_ + orow0 + col) = ll;
        packpair(oacc[nd][2] * i1, oacc[nd][3] * i1, hh, ll);
        *(uint32_t*)(Oh_ + orow1 + col) = hh;
        *(uint32_t*)(Ol_ + orow1 + col) = ll;
    }
}

// ---------------------------------------------------------------------------

extern "C" void kernel_launch(void* const* d_in, const int* in_sizes, int n_in,
                              void* d_out, int out_size) {
    const float* x  = (const float*)d_in[0];
    const float* qw = (const float*)d_in[1];
    const float* kw = (const float*)d_in[2];
    const float* vw = (const float*)d_in[3];
    const float* ow = (const float*)d_in[4];
    float* out = (float*)d_out;

    __half *xh,*xl,*w,*owp,*qh,*ql,*kv,*ath,*atl;
    cudaGetSymbolAddress((void**)&xh,  g_xh);  cudaGetSymbolAddress((void**)&xl,  g_xl);
    cudaGetSymbolAddress((void**)&w,   g_w);   cudaGetSymbolAddress((void**)&owp, g_ow);
    cudaGetSymbolAddress((void**)&qh,  g_qh);  cudaGetSymbolAddress((void**)&ql,  g_ql);
    cudaGetSymbolAddress((void**)&kv,  g_kv);
    cudaGetSymbolAddress((void**)&ath, g_ath); cudaGetSymbolAddress((void**)&atl, g_atl);

    cudaFuncSetAttribute((const void*)gemm_f16<0>,
                         cudaFuncAttributeMaxDynamicSharedMemorySize, SMEM_NK);
    cudaFuncSetAttribute((const void*)gemm_f16<1>,
                         cudaFuncAttributeMaxDynamicSharedMemorySize, SMEM_NK);
    cudaFuncSetAttribute((const void*)flash_attn,
                         cudaFuncAttributeMaxDynamicSharedMemorySize, FSMEM);

    // 0) splits / rounds
    splitk<<<(BB*SS*HIDDEN/4 + 255)/256, 256>>>(x, xh, xl, BB*SS*HIDDEN/4);
    splitw_qkv<<<(NQKV*HIDDEN/4 + 255)/256, 256>>>(qw, kw, vw, w);
    roundk<<<(HIDDEN*HIDDEN/4 + 255)/256, 256>>>(ow, owp, HIDDEN*HIDDEN/4);

    // 1) fused QKV projection
    gemm_f16<0><<<dim3(NQKV/BN, (BB*SS)/BM), 256, SMEM_NK>>>(
        xh, xl, w, qh, ql, kv, nullptr);

    // 2) fused attention
    flash_attn<<<dim3(SS/TQ, BB*HEADS), 256, FSMEM>>>(
        qh, ql, kv, ath, atl);

    // 3) out = attn @ Ow^T
    gemm_f16<1><<<dim3(HIDDEN/BN, (BB*SS)/BM), 256, SMEM_NK>>>(
        ath, atl, owp, nullptr, nullptr, nullptr, out);
}